// round 1
// baseline (speedup 1.0000x reference)
#include <cuda_runtime.h>
#include <math.h>

// Problem constants (fixed shapes)
#define NN 50000
#define EE 200000
#define RR 3
#define FF 128
#define HH 256
#define PP 100000
#define NPAIRS (RR*EE + PP)   // 700000

// scratch layout (floats)
#define OFF_SC_OUT 0ull
#define OFF_SC_IN  150000ull
#define OFF_AGG1   300000ull            // [N][R][F] = 19,200,000
#define OFF_AGG2   19500000ull          // [N][R][H] = 38,400,000
#define OFF_H1     57900000ull          // [N][H]    = 12,800,000
#define OFF_H2     70700000ull          // [N][F]    =  6,400,000
#define OFF_U      77100000ull
#define OFF_V      77150000ull
#define OFF_BS1    77200000ull
#define OFF_BS2    77200256ull
#define SCRATCH_TOTAL 77200384ull
#define ZERO_FLOATS 57900000ull         // sc_out + sc_in + agg1 + agg2

__device__ float g_scratch[SCRATCH_TOTAL];

// ---------------------------------------------------------------- zero
__global__ void zero_kernel() {
    size_t i = (size_t)blockIdx.x * blockDim.x + threadIdx.x;
    if (i < ZERO_FLOATS / 4) {
        reinterpret_cast<float4*>(g_scratch)[i] = make_float4(0.f, 0.f, 0.f, 0.f);
    }
}

// ---------------------------------------------------------------- bias sums
__global__ void bias_kernel(const float* __restrict__ b1, const float* __restrict__ b2) {
    int t = threadIdx.x;
    if (t < HH) {
        g_scratch[OFF_BS1 + t] = b1[t] + b1[HH + t] + b1[2 * HH + t];
    } else {
        int h = t - HH;
        g_scratch[OFF_BS2 + h] = b2[h] + b2[FF + h] + b2[2 * FF + h];
    }
}

// ---------------------------------------------------------------- degrees
__global__ void deg_kernel(const int* __restrict__ ei) {
    int i = blockIdx.x * blockDim.x + threadIdx.x;
    if (i >= RR * EE) return;
    int r = i / EE, e = i - r * EE;
    int src = ei[(size_t)r * 2 * EE + e];
    int dst = ei[(size_t)r * 2 * EE + EE + e];
    atomicAdd(&g_scratch[OFF_SC_OUT + (size_t)r * NN + src], 1.f);
    atomicAdd(&g_scratch[OFF_SC_IN  + (size_t)r * NN + dst], 1.f);
}

__global__ void rsq_kernel() {
    int i = blockIdx.x * blockDim.x + threadIdx.x;
    if (i < 2 * RR * NN) {
        float v = g_scratch[i];
        g_scratch[i] = rsqrtf(fmaxf(v, 1.f));
    }
}

// ---------------------------------------------------------------- scatter layer 1 (x -> agg1)
__device__ __forceinline__ void red_v4(float* p, float4 v) {
    asm volatile("red.global.add.v4.f32 [%0], {%1,%2,%3,%4};"
                 :: "l"(p), "f"(v.x), "f"(v.y), "f"(v.z), "f"(v.w) : "memory");
}

__global__ void scatter1_kernel(const int* __restrict__ ei, const float* __restrict__ x) {
    int w = (blockIdx.x * blockDim.x + threadIdx.x) >> 5;
    int lane = threadIdx.x & 31;
    if (w >= RR * EE) return;
    int r = w / EE, e = w - r * EE;
    int src = ei[(size_t)r * 2 * EE + e];
    int dst = ei[(size_t)r * 2 * EE + EE + e];
    float s = g_scratch[OFF_SC_OUT + (size_t)r * NN + src];
    float4 v = reinterpret_cast<const float4*>(x)[(size_t)src * 32 + lane];
    v.x *= s; v.y *= s; v.z *= s; v.w *= s;
    red_v4(&g_scratch[OFF_AGG1 + (size_t)dst * (RR * FF) + r * FF + lane * 4], v);
}

// ---------------------------------------------------------------- scatter layer 2 (h1 -> agg2)
__global__ void scatter2_kernel(const int* __restrict__ ei) {
    int w = (blockIdx.x * blockDim.x + threadIdx.x) >> 5;
    int lane = threadIdx.x & 31;
    if (w >= RR * EE) return;
    int r = w / EE, e = w - r * EE;
    int src = ei[(size_t)r * 2 * EE + e];
    int dst = ei[(size_t)r * 2 * EE + EE + e];
    float s = g_scratch[OFF_SC_OUT + (size_t)r * NN + src];
    const float4* h1v = reinterpret_cast<const float4*>(&g_scratch[OFF_H1]);
    float4 v0 = h1v[(size_t)src * 64 + lane];
    float4 v1 = h1v[(size_t)src * 64 + 32 + lane];
    v0.x *= s; v0.y *= s; v0.z *= s; v0.w *= s;
    v1.x *= s; v1.y *= s; v1.z *= s; v1.w *= s;
    size_t base = OFF_AGG2 + (size_t)dst * (RR * HH) + r * HH;
    red_v4(&g_scratch[base + lane * 4], v0);
    red_v4(&g_scratch[base + FF + lane * 4], v1);
}

// ---------------------------------------------------------------- dst-side degree scaling
__global__ void scaleA1_kernel() {   // agg1[n][r][f] *= sc_in[r][n]
    int i = blockIdx.x * blockDim.x + threadIdx.x;   // float4 index
    if (i >= NN * 96) return;
    int n = i / 96;
    int r = (i - n * 96) >> 5;       // 32 float4 per relation block
    float s = g_scratch[OFF_SC_IN + (size_t)r * NN + n];
    float4* p = reinterpret_cast<float4*>(&g_scratch[OFF_AGG1]) + i;
    float4 v = *p;
    v.x *= s; v.y *= s; v.z *= s; v.w *= s;
    *p = v;
}

__global__ void scaleA2_kernel() {   // agg2[n][r][h] *= sc_in[r][n]
    int i = blockIdx.x * blockDim.x + threadIdx.x;
    if (i >= NN * 192) return;
    int n = i / 192;
    int r = (i - n * 192) >> 6;      // 64 float4 per relation block
    float s = g_scratch[OFF_SC_IN + (size_t)r * NN + n];
    float4* p = reinterpret_cast<float4*>(&g_scratch[OFF_AGG2]) + i;
    float4 v = *p;
    v.x *= s; v.y *= s; v.z *= s; v.w *= s;
    *p = v;
}

// ---------------------------------------------------------------- fp32 SIMT GEMM
// C[M,Ncol] = (A[M,K] @ B[K,Ncol] + bias[Ncol]) / 3, optional relu
__global__ __launch_bounds__(256) void gemm_kernel(
    const float* __restrict__ A, const float* __restrict__ B,
    const float* __restrict__ bias, float* __restrict__ C,
    int M, int K, int Ncol, int doRelu)
{
    __shared__ float As[16][128];
    __shared__ float Bs[16][64];
    int tid = threadIdx.x;
    int tx = tid & 15, ty = tid >> 4;
    int bm = blockIdx.y * 128, bn = blockIdx.x * 64;
    float acc[8][4];
    #pragma unroll
    for (int i = 0; i < 8; i++)
        #pragma unroll
        for (int j = 0; j < 4; j++) acc[i][j] = 0.f;

    int arow = tid >> 2, akq = tid & 3;
    int brow = tid >> 4, bcol = tid & 15;

    for (int k0 = 0; k0 < K; k0 += 16) {
        #pragma unroll
        for (int p = 0; p < 2; p++) {
            int m = bm + p * 64 + arow;
            float4 a = make_float4(0.f, 0.f, 0.f, 0.f);
            if (m < M) a = *reinterpret_cast<const float4*>(A + (size_t)m * K + k0 + akq * 4);
            As[akq * 4 + 0][p * 64 + arow] = a.x;
            As[akq * 4 + 1][p * 64 + arow] = a.y;
            As[akq * 4 + 2][p * 64 + arow] = a.z;
            As[akq * 4 + 3][p * 64 + arow] = a.w;
        }
        *reinterpret_cast<float4*>(&Bs[brow][bcol * 4]) =
            *reinterpret_cast<const float4*>(B + (size_t)(k0 + brow) * Ncol + bn + bcol * 4);
        __syncthreads();
        #pragma unroll
        for (int k = 0; k < 16; k++) {
            float4 a0 = *reinterpret_cast<float4*>(&As[k][ty * 8]);
            float4 a1 = *reinterpret_cast<float4*>(&As[k][ty * 8 + 4]);
            float4 b4 = *reinterpret_cast<float4*>(&Bs[k][tx * 4]);
            float ar[8] = {a0.x, a0.y, a0.z, a0.w, a1.x, a1.y, a1.z, a1.w};
            float br[4] = {b4.x, b4.y, b4.z, b4.w};
            #pragma unroll
            for (int i = 0; i < 8; i++)
                #pragma unroll
                for (int j = 0; j < 4; j++)
                    acc[i][j] = fmaf(ar[i], br[j], acc[i][j]);
        }
        __syncthreads();
    }

    float4 bb = *reinterpret_cast<const float4*>(bias + bn + tx * 4);
    float bsv[4] = {bb.x, bb.y, bb.z, bb.w};
    const float inv3 = (1.f / 3.f);
    #pragma unroll
    for (int i = 0; i < 8; i++) {
        int m = bm + ty * 8 + i;
        if (m < M) {
            float4 o;
            o.x = (acc[i][0] + bsv[0]) * inv3;
            o.y = (acc[i][1] + bsv[1]) * inv3;
            o.z = (acc[i][2] + bsv[2]) * inv3;
            o.w = (acc[i][3] + bsv[3]) * inv3;
            if (doRelu) {
                o.x = fmaxf(o.x, 0.f); o.y = fmaxf(o.y, 0.f);
                o.z = fmaxf(o.z, 0.f); o.w = fmaxf(o.w, 0.f);
            }
            *reinterpret_cast<float4*>(C + (size_t)m * Ncol + bn + tx * 4) = o;
        }
    }
}

// ---------------------------------------------------------------- per-node u/v
__global__ void uv_kernel(const float* __restrict__ Wlin) {
    int w = (blockIdx.x * blockDim.x + threadIdx.x) >> 5;
    int lane = threadIdx.x & 31;
    if (w >= NN) return;
    const float4* h2v = reinterpret_cast<const float4*>(&g_scratch[OFF_H2]);
    float4 h = h2v[(size_t)w * 32 + lane];
    h.x = fmaxf(h.x, 0.f); h.y = fmaxf(h.y, 0.f);
    h.z = fmaxf(h.z, 0.f); h.w = fmaxf(h.w, 0.f);
    const float4* wv = reinterpret_cast<const float4*>(Wlin);
    float4 wl = wv[lane];
    float4 wh = wv[32 + lane];
    float su = h.x * wl.x + h.y * wl.y + h.z * wl.z + h.w * wl.w;
    float sv = h.x * wh.x + h.y * wh.y + h.z * wh.z + h.w * wh.w;
    #pragma unroll
    for (int o = 16; o > 0; o >>= 1) {
        su += __shfl_down_sync(0xffffffffu, su, o);
        sv += __shfl_down_sync(0xffffffffu, sv, o);
    }
    if (lane == 0) {
        g_scratch[OFF_U + w] = su;
        g_scratch[OFF_V + w] = sv;
    }
}

// ---------------------------------------------------------------- pair head
__global__ void pairs_kernel(const int* __restrict__ ei, const int* __restrict__ np,
                             const float* __restrict__ blin, float* __restrict__ out) {
    int i = blockIdx.x * blockDim.x + threadIdx.x;
    if (i >= NPAIRS) return;
    int src, dst;
    if (i < RR * EE) {
        int r = i / EE, e = i - r * EE;
        src = ei[(size_t)r * 2 * EE + e];
        dst = ei[(size_t)r * 2 * EE + EE + e];
    } else {
        int j = i - RR * EE;
        src = np[2 * j];
        dst = np[2 * j + 1];
    }
    float z = g_scratch[OFF_U + src] + g_scratch[OFF_V + dst] + blin[0];
    out[i] = 1.f / (1.f + expf(-z));
}

// ---------------------------------------------------------------- launch
extern "C" void kernel_launch(void* const* d_in, const int* in_sizes, int n_in,
                              void* d_out, int out_size) {
    const float* x    = (const float*)d_in[0];
    const int*   ei   = (const int*)  d_in[1];
    const int*   np   = (const int*)  d_in[2];
    const float* W1   = (const float*)d_in[3];  // (R,F,H) flat = [384,256]
    const float* b1   = (const float*)d_in[4];
    const float* W2   = (const float*)d_in[5];  // (R,H,F) flat = [768,128]
    const float* b2   = (const float*)d_in[6];
    const float* Wlin = (const float*)d_in[7];
    const float* blin = (const float*)d_in[8];
    float* out = (float*)d_out;

    float* agg1 = nullptr; float* agg2 = nullptr;
    float* h1 = nullptr;   float* h2 = nullptr;
    float* bs1 = nullptr;  float* bs2 = nullptr;
    {
        // resolve device symbol address once-equivalent (cheap, per-call, capture-safe)
        void* base = nullptr;
        cudaGetSymbolAddress(&base, g_scratch);
        float* fb = (float*)base;
        agg1 = fb + OFF_AGG1; agg2 = fb + OFF_AGG2;
        h1 = fb + OFF_H1; h2 = fb + OFF_H2;
        bs1 = fb + OFF_BS1; bs2 = fb + OFF_BS2;
    }

    // 1. zero degree counters + aggregation buffers
    zero_kernel<<<(unsigned)((ZERO_FLOATS / 4 + 255) / 256), 256>>>();
    // 2. bias sums
    bias_kernel<<<1, HH + FF>>>(b1, b2);
    // 3. degrees -> rsqrt scales
    deg_kernel<<<(RR * EE + 255) / 256, 256>>>(ei);
    rsq_kernel<<<(2 * RR * NN + 255) / 256, 256>>>();
    // 4. layer-1 scatter (src-scaled x into agg1[n][r][f])
    scatter1_kernel<<<(RR * EE * 32 + 255) / 256, 256>>>(ei, x);
    // 5. dst scaling
    scaleA1_kernel<<<(NN * 96 + 255) / 256, 256>>>();
    // 6. GEMM1: h1 = relu((agg1 @ W1flat + bs1)/3)   [50000,384]x[384,256]
    gemm_kernel<<<dim3(HH / 64, (NN + 127) / 128), 256>>>(agg1, W1, bs1, h1, NN, RR * FF, HH, 1);
    // 7. layer-2 scatter
    scatter2_kernel<<<(RR * EE * 32 + 255) / 256, 256>>>(ei);
    // 8. dst scaling
    scaleA2_kernel<<<(NN * 192 + 255) / 256, 256>>>();
    // 9. GEMM2: h2 = (agg2 @ W2flat + bs2)/3         [50000,768]x[768,128]
    gemm_kernel<<<dim3(FF / 64, (NN + 127) / 128), 256>>>(agg2, W2, bs2, h2, NN, RR * HH, FF, 0);
    // 10. per-node u/v partial dot products
    uv_kernel<<<(NN * 32 + 255) / 256, 256>>>(Wlin);
    // 11. pair outputs
    pairs_kernel<<<(NPAIRS + 255) / 256, 256>>>(ei, np, blin, out);
}

// round 2
// speedup vs baseline: 1.8742x; 1.8742x over previous
#include <cuda_runtime.h>
#include <math.h>

// Problem constants (fixed shapes)
#define NN 50000
#define EE 200000
#define RR 3
#define FF 128
#define HH 256
#define PP 100000
#define NPAIRS (RR*EE + PP)   // 700000

// scratch layout (floats) — [zeroed region | persistent-per-run region]
#define OFF_SC_OUT 0ull
#define OFF_SC_IN  150000ull
#define OFF_AGG    300000ull            // [N][R*F]=19.2M ; reused as z2 [N][R*F]
#define OFF_ACC2   19500000ull          // [N][F] = 6.4M
#define ZERO_FLOATS 25900000ull
#define OFF_H1     25900000ull          // [N][H] = 12.8M
#define OFF_U      38700000ull
#define OFF_V      38750000ull
#define OFF_BS1    38800000ull          // 256
#define OFF_BS2    38800256ull          // 128
#define OFF_W2P    38800384ull          // [H][R*F] = 98304
#define SCRATCH_TOTAL 38898688ull

__device__ float g_scratch[SCRATCH_TOTAL];

// ---------------------------------------------------------------- zero
__global__ void zero_kernel() {
    size_t i = (size_t)blockIdx.x * blockDim.x + threadIdx.x;
    if (i < ZERO_FLOATS / 4) {
        reinterpret_cast<float4*>(g_scratch)[i] = make_float4(0.f, 0.f, 0.f, 0.f);
    }
}

// ---------------------------------------------------------------- bias sums
__global__ void bias_kernel(const float* __restrict__ b1, const float* __restrict__ b2) {
    int t = threadIdx.x;
    if (t < HH) {
        g_scratch[OFF_BS1 + t] = b1[t] + b1[HH + t] + b1[2 * HH + t];
    } else if (t < HH + FF) {
        int h = t - HH;
        g_scratch[OFF_BS2 + h] = b2[h] + b2[FF + h] + b2[2 * FF + h];
    }
}

// ---------------------------------------------------------------- W2 pack: W2[r][h][f] -> W2P[h][r*F+f]
__global__ void w2pack_kernel(const float* __restrict__ W2) {
    int i = blockIdx.x * blockDim.x + threadIdx.x;
    if (i >= RR * HH * FF) return;
    int r = i / (HH * FF);
    int rem = i - r * (HH * FF);
    int h = rem / FF;
    int f = rem - h * FF;
    g_scratch[OFF_W2P + (size_t)h * (RR * FF) + r * FF + f] = W2[i];
}

// ---------------------------------------------------------------- degrees
__global__ void deg_kernel(const int* __restrict__ ei) {
    int i = blockIdx.x * blockDim.x + threadIdx.x;
    if (i >= RR * EE) return;
    int r = i / EE, e = i - r * EE;
    int src = ei[(size_t)r * 2 * EE + e];
    int dst = ei[(size_t)r * 2 * EE + EE + e];
    atomicAdd(&g_scratch[OFF_SC_OUT + (size_t)r * NN + src], 1.f);
    atomicAdd(&g_scratch[OFF_SC_IN  + (size_t)r * NN + dst], 1.f);
}

__global__ void rsq_kernel() {
    int i = blockIdx.x * blockDim.x + threadIdx.x;
    if (i < 2 * RR * NN) {
        float v = g_scratch[i];
        g_scratch[i] = rsqrtf(fmaxf(v, 1.f));
    }
}

// ---------------------------------------------------------------- scatter helpers
__device__ __forceinline__ void red_v4(float* p, float4 v) {
    asm volatile("red.global.add.v4.f32 [%0], {%1,%2,%3,%4};"
                 :: "l"(p), "f"(v.x), "f"(v.y), "f"(v.z), "f"(v.w) : "memory");
}

// ---------------------------------------------------------------- scatter layer 1 (x -> agg, both scales folded)
__global__ void scatter1_kernel(const int* __restrict__ ei, const float* __restrict__ x) {
    int w = (blockIdx.x * blockDim.x + threadIdx.x) >> 5;
    int lane = threadIdx.x & 31;
    if (w >= RR * EE) return;
    int r = w / EE, e = w - r * EE;
    int src = ei[(size_t)r * 2 * EE + e];
    int dst = ei[(size_t)r * 2 * EE + EE + e];
    float s = g_scratch[OFF_SC_OUT + (size_t)r * NN + src]
            * g_scratch[OFF_SC_IN  + (size_t)r * NN + dst];
    float4 v = reinterpret_cast<const float4*>(x)[(size_t)src * 32 + lane];
    v.x *= s; v.y *= s; v.z *= s; v.w *= s;
    red_v4(&g_scratch[OFF_AGG + (size_t)dst * (RR * FF) + r * FF + lane * 4], v);
}

// ---------------------------------------------------------------- scatter layer 2 (z -> acc2, both scales folded)
// z[src][r*F..r*F+127] is the per-relation GEMM output; accumulate into [N][F]
__global__ void scatter2_kernel(const int* __restrict__ ei) {
    int w = (blockIdx.x * blockDim.x + threadIdx.x) >> 5;
    int lane = threadIdx.x & 31;
    if (w >= RR * EE) return;
    int r = w / EE, e = w - r * EE;
    int src = ei[(size_t)r * 2 * EE + e];
    int dst = ei[(size_t)r * 2 * EE + EE + e];
    float s = g_scratch[OFF_SC_OUT + (size_t)r * NN + src]
            * g_scratch[OFF_SC_IN  + (size_t)r * NN + dst];
    const float4* zv = reinterpret_cast<const float4*>(&g_scratch[OFF_AGG]);
    float4 v = zv[(size_t)src * 96 + r * 32 + lane];
    v.x *= s; v.y *= s; v.z *= s; v.w *= s;
    red_v4(&g_scratch[OFF_ACC2 + (size_t)dst * FF + lane * 4], v);
}

// ---------------------------------------------------------------- fp32 SIMT GEMM
// C[M,Ncol] = op((A[M,K] @ B[K,Ncol] + bias) * scale), op = relu?
__global__ __launch_bounds__(256) void gemm_kernel(
    const float* __restrict__ A, const float* __restrict__ B,
    const float* __restrict__ bias, float* __restrict__ C,
    int M, int K, int Ncol, int doRelu, float scale)
{
    __shared__ float As[16][128];
    __shared__ float Bs[16][64];
    int tid = threadIdx.x;
    int tx = tid & 15, ty = tid >> 4;
    int bm = blockIdx.y * 128, bn = blockIdx.x * 64;
    float acc[8][4];
    #pragma unroll
    for (int i = 0; i < 8; i++)
        #pragma unroll
        for (int j = 0; j < 4; j++) acc[i][j] = 0.f;

    int arow = tid >> 2, akq = tid & 3;
    int brow = tid >> 4, bcol = tid & 15;

    for (int k0 = 0; k0 < K; k0 += 16) {
        #pragma unroll
        for (int p = 0; p < 2; p++) {
            int m = bm + p * 64 + arow;
            float4 a = make_float4(0.f, 0.f, 0.f, 0.f);
            if (m < M) a = *reinterpret_cast<const float4*>(A + (size_t)m * K + k0 + akq * 4);
            As[akq * 4 + 0][p * 64 + arow] = a.x;
            As[akq * 4 + 1][p * 64 + arow] = a.y;
            As[akq * 4 + 2][p * 64 + arow] = a.z;
            As[akq * 4 + 3][p * 64 + arow] = a.w;
        }
        *reinterpret_cast<float4*>(&Bs[brow][bcol * 4]) =
            *reinterpret_cast<const float4*>(B + (size_t)(k0 + brow) * Ncol + bn + bcol * 4);
        __syncthreads();
        #pragma unroll
        for (int k = 0; k < 16; k++) {
            float4 a0 = *reinterpret_cast<float4*>(&As[k][ty * 8]);
            float4 a1 = *reinterpret_cast<float4*>(&As[k][ty * 8 + 4]);
            float4 b4 = *reinterpret_cast<float4*>(&Bs[k][tx * 4]);
            float ar[8] = {a0.x, a0.y, a0.z, a0.w, a1.x, a1.y, a1.z, a1.w};
            float br[4] = {b4.x, b4.y, b4.z, b4.w};
            #pragma unroll
            for (int i = 0; i < 8; i++)
                #pragma unroll
                for (int j = 0; j < 4; j++)
                    acc[i][j] = fmaf(ar[i], br[j], acc[i][j]);
        }
        __syncthreads();
    }

    float bsv[4] = {0.f, 0.f, 0.f, 0.f};
    if (bias) {
        float4 bb = *reinterpret_cast<const float4*>(bias + bn + tx * 4);
        bsv[0] = bb.x; bsv[1] = bb.y; bsv[2] = bb.z; bsv[3] = bb.w;
    }
    #pragma unroll
    for (int i = 0; i < 8; i++) {
        int m = bm + ty * 8 + i;
        if (m < M) {
            float4 o;
            o.x = (acc[i][0] + bsv[0]) * scale;
            o.y = (acc[i][1] + bsv[1]) * scale;
            o.z = (acc[i][2] + bsv[2]) * scale;
            o.w = (acc[i][3] + bsv[3]) * scale;
            if (doRelu) {
                o.x = fmaxf(o.x, 0.f); o.y = fmaxf(o.y, 0.f);
                o.z = fmaxf(o.z, 0.f); o.w = fmaxf(o.w, 0.f);
            }
            *reinterpret_cast<float4*>(C + (size_t)m * Ncol + bn + tx * 4) = o;
        }
    }
}

// ---------------------------------------------------------------- per-node u/v (fused h2 epilogue)
__global__ void uv_kernel(const float* __restrict__ Wlin) {
    int w = (blockIdx.x * blockDim.x + threadIdx.x) >> 5;
    int lane = threadIdx.x & 31;
    if (w >= NN) return;
    const float inv3 = (1.f / 3.f);
    const float4* av = reinterpret_cast<const float4*>(&g_scratch[OFF_ACC2]);
    float4 h = av[(size_t)w * 32 + lane];
    float4 bb = *reinterpret_cast<const float4*>(&g_scratch[OFF_BS2 + lane * 4]);
    h.x = fmaxf((h.x + bb.x) * inv3, 0.f);
    h.y = fmaxf((h.y + bb.y) * inv3, 0.f);
    h.z = fmaxf((h.z + bb.z) * inv3, 0.f);
    h.w = fmaxf((h.w + bb.w) * inv3, 0.f);
    const float4* wv = reinterpret_cast<const float4*>(Wlin);
    float4 wl = wv[lane];
    float4 wh = wv[32 + lane];
    float su = h.x * wl.x + h.y * wl.y + h.z * wl.z + h.w * wl.w;
    float sv = h.x * wh.x + h.y * wh.y + h.z * wh.z + h.w * wh.w;
    #pragma unroll
    for (int o = 16; o > 0; o >>= 1) {
        su += __shfl_down_sync(0xffffffffu, su, o);
        sv += __shfl_down_sync(0xffffffffu, sv, o);
    }
    if (lane == 0) {
        g_scratch[OFF_U + w] = su;
        g_scratch[OFF_V + w] = sv;
    }
}

// ---------------------------------------------------------------- pair head
__global__ void pairs_kernel(const int* __restrict__ ei, const int* __restrict__ np,
                             const float* __restrict__ blin, float* __restrict__ out) {
    int i = blockIdx.x * blockDim.x + threadIdx.x;
    if (i >= NPAIRS) return;
    int src, dst;
    if (i < RR * EE) {
        int r = i / EE, e = i - r * EE;
        src = ei[(size_t)r * 2 * EE + e];
        dst = ei[(size_t)r * 2 * EE + EE + e];
    } else {
        int j = i - RR * EE;
        src = np[2 * j];
        dst = np[2 * j + 1];
    }
    float z = g_scratch[OFF_U + src] + g_scratch[OFF_V + dst] + blin[0];
    out[i] = 1.f / (1.f + expf(-z));
}

// ---------------------------------------------------------------- launch
extern "C" void kernel_launch(void* const* d_in, const int* in_sizes, int n_in,
                              void* d_out, int out_size) {
    const float* x    = (const float*)d_in[0];
    const int*   ei   = (const int*)  d_in[1];
    const int*   np   = (const int*)  d_in[2];
    const float* W1   = (const float*)d_in[3];  // (R,F,H) flat = [384,256]
    const float* b1   = (const float*)d_in[4];
    const float* W2   = (const float*)d_in[5];  // (R,H,F)
    const float* b2   = (const float*)d_in[6];
    const float* Wlin = (const float*)d_in[7];
    const float* blin = (const float*)d_in[8];
    float* out = (float*)d_out;

    void* base = nullptr;
    cudaGetSymbolAddress(&base, g_scratch);
    float* fb = (float*)base;
    float* agg  = fb + OFF_AGG;
    float* h1   = fb + OFF_H1;
    float* bs1  = fb + OFF_BS1;
    float* w2p  = fb + OFF_W2P;

    // 1. zero scales + agg + acc2
    zero_kernel<<<(unsigned)((ZERO_FLOATS / 4 + 255) / 256), 256>>>();
    // 2. bias sums + W2 pack
    bias_kernel<<<2, 256>>>(b1, b2);
    w2pack_kernel<<<(RR * HH * FF + 255) / 256, 256>>>(W2);
    // 3. degrees -> rsqrt scales
    deg_kernel<<<(RR * EE + 255) / 256, 256>>>(ei);
    rsq_kernel<<<(2 * RR * NN + 255) / 256, 256>>>();
    // 4. layer-1 scatter (both scales folded) into agg[n][r*F+f]
    scatter1_kernel<<<(RR * EE * 32 + 255) / 256, 256>>>(ei, x);
    // 5. GEMM1: h1 = relu((agg @ W1flat + bs1)/3)   [50000,384]x[384,256]
    gemm_kernel<<<dim3(HH / 64, (NN + 127) / 128), 256>>>(agg, W1, bs1, h1, NN, RR * FF, HH, 1, 1.f / 3.f);
    // 6. GEMM2a: z = h1 @ W2P   [50000,256]x[256,384] -> reuse agg buffer
    gemm_kernel<<<dim3((RR * FF) / 64, (NN + 127) / 128), 256>>>(h1, w2p, nullptr, agg, NN, HH, RR * FF, 0, 1.f);
    // 7. layer-2 scatter (both scales folded) into acc2[n][f]
    scatter2_kernel<<<(RR * EE * 32 + 255) / 256, 256>>>(ei);
    // 8. per-node u/v (fused h2 epilogue: +bias, /3, relu, dot Wlin)
    uv_kernel<<<(NN * 32 + 255) / 256, 256>>>(Wlin);
    // 9. pair outputs
    pairs_kernel<<<(NPAIRS + 255) / 256, 256>>>(ei, np, blin, out);
}

// round 3
// speedup vs baseline: 2.8687x; 1.5306x over previous
#include <cuda_runtime.h>
#include <math.h>

// Problem constants (fixed shapes)
#define NN 50000
#define EE 200000
#define RR 3
#define FF 128
#define HH 256
#define PP 100000
#define NPAIRS (RR*EE + PP)   // 700000

// scratch layout (floats) — [zeroed region | persistent-per-run region]
#define OFF_SC_OUT 0ull
#define OFF_SC_IN  150000ull
#define OFF_AGG    300000ull            // [N][R*F]=19.2M ; reused as z2 [N][R*F]
#define OFF_ACC2   19500000ull          // [N][F] = 6.4M
#define ZERO_FLOATS 25900000ull
#define OFF_H1     25900000ull          // [N][H] = 12.8M
#define OFF_U      38700000ull
#define OFF_V      38750000ull
#define OFF_BS1    38800000ull          // 256
#define OFF_BS2    38800256ull          // 128
#define OFF_W2P    38800384ull          // [H][R*F] = 98304
#define SCRATCH_TOTAL 38898688ull

__device__ float g_scratch[SCRATCH_TOTAL];

// ---------------------------------------------------------------- zero
__global__ void zero_kernel() {
    size_t i = (size_t)blockIdx.x * blockDim.x + threadIdx.x;
    if (i < ZERO_FLOATS / 4) {
        reinterpret_cast<float4*>(g_scratch)[i] = make_float4(0.f, 0.f, 0.f, 0.f);
    }
}

// ---------------------------------------------------------------- bias sums
__global__ void bias_kernel(const float* __restrict__ b1, const float* __restrict__ b2) {
    int t = blockIdx.x * blockDim.x + threadIdx.x;
    if (t < HH) {
        g_scratch[OFF_BS1 + t] = b1[t] + b1[HH + t] + b1[2 * HH + t];
    } else if (t < HH + FF) {
        int h = t - HH;
        g_scratch[OFF_BS2 + h] = b2[h] + b2[FF + h] + b2[2 * FF + h];
    }
}

// ---------------------------------------------------------------- W2 pack: W2[r][h][f] -> W2P[h][r*F+f]
__global__ void w2pack_kernel(const float* __restrict__ W2) {
    int i = blockIdx.x * blockDim.x + threadIdx.x;
    if (i >= RR * HH * FF) return;
    int r = i / (HH * FF);
    int rem = i - r * (HH * FF);
    int h = rem / FF;
    int f = rem - h * FF;
    g_scratch[OFF_W2P + (size_t)h * (RR * FF) + r * FF + f] = W2[i];
}

// ---------------------------------------------------------------- degrees
__global__ void deg_kernel(const int* __restrict__ ei) {
    int i = blockIdx.x * blockDim.x + threadIdx.x;
    if (i >= RR * EE) return;
    int r = i / EE, e = i - r * EE;
    int src = ei[(size_t)r * 2 * EE + e];
    int dst = ei[(size_t)r * 2 * EE + EE + e];
    atomicAdd(&g_scratch[OFF_SC_OUT + (size_t)r * NN + src], 1.f);
    atomicAdd(&g_scratch[OFF_SC_IN  + (size_t)r * NN + dst], 1.f);
}

__global__ void rsq_kernel() {
    int i = blockIdx.x * blockDim.x + threadIdx.x;
    if (i < 2 * RR * NN) {
        float v = g_scratch[i];
        g_scratch[i] = rsqrtf(fmaxf(v, 1.f));
    }
}

// ---------------------------------------------------------------- scatter helpers
__device__ __forceinline__ void red_v4(float* p, float4 v) {
    asm volatile("red.global.add.v4.f32 [%0], {%1,%2,%3,%4};"
                 :: "l"(p), "f"(v.x), "f"(v.y), "f"(v.z), "f"(v.w) : "memory");
}

// ---------------------------------------------------------------- scatter layer 1 (x -> agg, both scales folded)
__global__ void scatter1_kernel(const int* __restrict__ ei, const float* __restrict__ x) {
    int w = (blockIdx.x * blockDim.x + threadIdx.x) >> 5;
    int lane = threadIdx.x & 31;
    if (w >= RR * EE) return;
    int r = w / EE, e = w - r * EE;
    int src = ei[(size_t)r * 2 * EE + e];
    int dst = ei[(size_t)r * 2 * EE + EE + e];
    float s = g_scratch[OFF_SC_OUT + (size_t)r * NN + src]
            * g_scratch[OFF_SC_IN  + (size_t)r * NN + dst];
    float4 v = reinterpret_cast<const float4*>(x)[(size_t)src * 32 + lane];
    v.x *= s; v.y *= s; v.z *= s; v.w *= s;
    red_v4(&g_scratch[OFF_AGG + (size_t)dst * (RR * FF) + r * FF + lane * 4], v);
}

// ---------------------------------------------------------------- scatter layer 2 (z -> acc2, both scales folded)
__global__ void scatter2_kernel(const int* __restrict__ ei) {
    int w = (blockIdx.x * blockDim.x + threadIdx.x) >> 5;
    int lane = threadIdx.x & 31;
    if (w >= RR * EE) return;
    int r = w / EE, e = w - r * EE;
    int src = ei[(size_t)r * 2 * EE + e];
    int dst = ei[(size_t)r * 2 * EE + EE + e];
    float s = g_scratch[OFF_SC_OUT + (size_t)r * NN + src]
            * g_scratch[OFF_SC_IN  + (size_t)r * NN + dst];
    const float4* zv = reinterpret_cast<const float4*>(&g_scratch[OFF_AGG]);
    float4 v = zv[(size_t)src * 96 + r * 32 + lane];
    v.x *= s; v.y *= s; v.z *= s; v.w *= s;
    red_v4(&g_scratch[OFF_ACC2 + (size_t)dst * FF + lane * 4], v);
}

// ---------------------------------------------------------------- tf32 tensor-core GEMM
// C[M,Ncol] = op((A[M,K] @ B[K,Ncol] + bias) * scale)
// 128x64 block tile, BK=16, 8 warps each 32x32 (2 m16 x 4 n8 mma tiles)
#define BM 128
#define BN 64
#define BK 16
#define APAD 8
#define BPAD 8

__device__ __forceinline__ unsigned f2tf32(float f) {
    unsigned u;
    asm("cvt.rna.tf32.f32 %0, %1;" : "=r"(u) : "f"(f));
    return u;
}

__device__ __forceinline__ void mma_tf32(float* d, const unsigned* a, const unsigned* b) {
    asm volatile("mma.sync.aligned.m16n8k8.row.col.f32.tf32.tf32.f32 "
                 "{%0,%1,%2,%3}, {%4,%5,%6,%7}, {%8,%9}, {%0,%1,%2,%3};"
                 : "+f"(d[0]), "+f"(d[1]), "+f"(d[2]), "+f"(d[3])
                 : "r"(a[0]), "r"(a[1]), "r"(a[2]), "r"(a[3]),
                   "r"(b[0]), "r"(b[1]));
}

__global__ __launch_bounds__(256) void gemm_tc_kernel(
    const float* __restrict__ A, const float* __restrict__ B,
    const float* __restrict__ bias, float* __restrict__ C,
    int M, int K, int Ncol, int doRelu, float scale)
{
    __shared__ float As[BK][BM + APAD];   // k-major
    __shared__ float Bs[BK][BN + BPAD];   // k-major

    int tid = threadIdx.x;
    int warp = tid >> 5;
    int lane = tid & 31;
    int wr = warp >> 1;        // 0..3 -> m offset 32*wr
    int wc = warp & 1;         // 0..1 -> n offset 32*wc
    int bm = blockIdx.y * BM, bn = blockIdx.x * BN;

    int tg = lane >> 2;        // 0..7  (thread group / row-in-frag)
    int tq = lane & 3;         // 0..3  (col-in-frag)

    float acc[2][4][4];
    #pragma unroll
    for (int i = 0; i < 2; i++)
        #pragma unroll
        for (int j = 0; j < 4; j++)
            #pragma unroll
            for (int q = 0; q < 4; q++) acc[i][j][q] = 0.f;

    // global-load indices
    int a_m = tid >> 2;        // 0..63 (two passes of 64 rows)
    int a_k4 = tid & 3;        // float4 along K
    int b_k = tid >> 4;        // 0..15
    int b_n4 = tid & 15;       // float4 along N

    for (int k0 = 0; k0 < K; k0 += BK) {
        // load A tile (transpose to k-major)
        #pragma unroll
        for (int p = 0; p < 2; p++) {
            int m = bm + p * 64 + a_m;
            float4 a = make_float4(0.f, 0.f, 0.f, 0.f);
            if (m < M) a = *reinterpret_cast<const float4*>(A + (size_t)m * K + k0 + a_k4 * 4);
            As[a_k4 * 4 + 0][p * 64 + a_m] = a.x;
            As[a_k4 * 4 + 1][p * 64 + a_m] = a.y;
            As[a_k4 * 4 + 2][p * 64 + a_m] = a.z;
            As[a_k4 * 4 + 3][p * 64 + a_m] = a.w;
        }
        // load B tile (already k-major rows)
        {
            float4 b = *reinterpret_cast<const float4*>(B + (size_t)(k0 + b_k) * Ncol + bn + b_n4 * 4);
            Bs[b_k][b_n4 * 4 + 0] = b.x;
            Bs[b_k][b_n4 * 4 + 1] = b.y;
            Bs[b_k][b_n4 * 4 + 2] = b.z;
            Bs[b_k][b_n4 * 4 + 3] = b.w;
        }
        __syncthreads();

        #pragma unroll
        for (int kk = 0; kk < BK; kk += 8) {
            unsigned af[2][4], bf[4][2];
            #pragma unroll
            for (int i = 0; i < 2; i++) {
                int mb = wr * 32 + i * 16;
                af[i][0] = f2tf32(As[kk + tq    ][mb + tg    ]);
                af[i][1] = f2tf32(As[kk + tq    ][mb + tg + 8]);
                af[i][2] = f2tf32(As[kk + tq + 4][mb + tg    ]);
                af[i][3] = f2tf32(As[kk + tq + 4][mb + tg + 8]);
            }
            #pragma unroll
            for (int j = 0; j < 4; j++) {
                int nb = wc * 32 + j * 8;
                bf[j][0] = f2tf32(Bs[kk + tq    ][nb + tg]);
                bf[j][1] = f2tf32(Bs[kk + tq + 4][nb + tg]);
            }
            #pragma unroll
            for (int i = 0; i < 2; i++)
                #pragma unroll
                for (int j = 0; j < 4; j++)
                    mma_tf32(acc[i][j], af[i], bf[j]);
        }
        __syncthreads();
    }

    // epilogue
    #pragma unroll
    for (int i = 0; i < 2; i++) {
        #pragma unroll
        for (int j = 0; j < 4; j++) {
            int col = bn + wc * 32 + j * 8 + tq * 2;
            float b0 = 0.f, b1 = 0.f;
            if (bias) { b0 = bias[col]; b1 = bias[col + 1]; }
            #pragma unroll
            for (int h = 0; h < 2; h++) {     // h=0 -> rows tg, h=1 -> rows tg+8
                int row = bm + wr * 32 + i * 16 + tg + h * 8;
                if (row < M) {
                    float o0 = (acc[i][j][2 * h + 0] + b0) * scale;
                    float o1 = (acc[i][j][2 * h + 1] + b1) * scale;
                    if (doRelu) { o0 = fmaxf(o0, 0.f); o1 = fmaxf(o1, 0.f); }
                    *reinterpret_cast<float2*>(C + (size_t)row * Ncol + col) = make_float2(o0, o1);
                }
            }
        }
    }
}

// ---------------------------------------------------------------- per-node u/v (fused h2 epilogue)
__global__ void uv_kernel(const float* __restrict__ Wlin) {
    int w = (blockIdx.x * blockDim.x + threadIdx.x) >> 5;
    int lane = threadIdx.x & 31;
    if (w >= NN) return;
    const float inv3 = (1.f / 3.f);
    const float4* av = reinterpret_cast<const float4*>(&g_scratch[OFF_ACC2]);
    float4 h = av[(size_t)w * 32 + lane];
    float4 bb = *reinterpret_cast<const float4*>(&g_scratch[OFF_BS2 + lane * 4]);
    h.x = fmaxf((h.x + bb.x) * inv3, 0.f);
    h.y = fmaxf((h.y + bb.y) * inv3, 0.f);
    h.z = fmaxf((h.z + bb.z) * inv3, 0.f);
    h.w = fmaxf((h.w + bb.w) * inv3, 0.f);
    const float4* wv = reinterpret_cast<const float4*>(Wlin);
    float4 wl = wv[lane];
    float4 wh = wv[32 + lane];
    float su = h.x * wl.x + h.y * wl.y + h.z * wl.z + h.w * wl.w;
    float sv = h.x * wh.x + h.y * wh.y + h.z * wh.z + h.w * wh.w;
    #pragma unroll
    for (int o = 16; o > 0; o >>= 1) {
        su += __shfl_down_sync(0xffffffffu, su, o);
        sv += __shfl_down_sync(0xffffffffu, sv, o);
    }
    if (lane == 0) {
        g_scratch[OFF_U + w] = su;
        g_scratch[OFF_V + w] = sv;
    }
}

// ---------------------------------------------------------------- pair head
__global__ void pairs_kernel(const int* __restrict__ ei, const int* __restrict__ np,
                             const float* __restrict__ blin, float* __restrict__ out) {
    int i = blockIdx.x * blockDim.x + threadIdx.x;
    if (i >= NPAIRS) return;
    int src, dst;
    if (i < RR * EE) {
        int r = i / EE, e = i - r * EE;
        src = ei[(size_t)r * 2 * EE + e];
        dst = ei[(size_t)r * 2 * EE + EE + e];
    } else {
        int j = i - RR * EE;
        src = np[2 * j];
        dst = np[2 * j + 1];
    }
    float z = g_scratch[OFF_U + src] + g_scratch[OFF_V + dst] + blin[0];
    out[i] = 1.f / (1.f + expf(-z));
}

// ---------------------------------------------------------------- launch
extern "C" void kernel_launch(void* const* d_in, const int* in_sizes, int n_in,
                              void* d_out, int out_size) {
    const float* x    = (const float*)d_in[0];
    const int*   ei   = (const int*)  d_in[1];
    const int*   np   = (const int*)  d_in[2];
    const float* W1   = (const float*)d_in[3];  // (R,F,H) flat = [384,256]
    const float* b1   = (const float*)d_in[4];
    const float* W2   = (const float*)d_in[5];  // (R,H,F)
    const float* b2   = (const float*)d_in[6];
    const float* Wlin = (const float*)d_in[7];
    const float* blin = (const float*)d_in[8];
    float* out = (float*)d_out;

    void* base = nullptr;
    cudaGetSymbolAddress(&base, g_scratch);
    float* fb = (float*)base;
    float* agg  = fb + OFF_AGG;
    float* h1   = fb + OFF_H1;
    float* bs1  = fb + OFF_BS1;
    float* w2p  = fb + OFF_W2P;

    // 1. zero scales + agg + acc2
    zero_kernel<<<(unsigned)((ZERO_FLOATS / 4 + 255) / 256), 256>>>();
    // 2. bias sums + W2 pack
    bias_kernel<<<2, 256>>>(b1, b2);
    w2pack_kernel<<<(RR * HH * FF + 255) / 256, 256>>>(W2);
    // 3. degrees -> rsqrt scales
    deg_kernel<<<(RR * EE + 255) / 256, 256>>>(ei);
    rsq_kernel<<<(2 * RR * NN + 255) / 256, 256>>>();
    // 4. layer-1 scatter (both scales folded) into agg[n][r*F+f]
    scatter1_kernel<<<(RR * EE * 32 + 255) / 256, 256>>>(ei, x);
    // 5. GEMM1: h1 = relu((agg @ W1flat + bs1)/3)   [50000,384]x[384,256]
    gemm_tc_kernel<<<dim3(HH / BN, (NN + BM - 1) / BM), 256>>>(agg, W1, bs1, h1, NN, RR * FF, HH, 1, 1.f / 3.f);
    // 6. GEMM2a: z = h1 @ W2P   [50000,256]x[256,384] -> reuse agg buffer
    gemm_tc_kernel<<<dim3((RR * FF) / BN, (NN + BM - 1) / BM), 256>>>(h1, w2p, nullptr, agg, NN, HH, RR * FF, 0, 1.f);
    // 7. layer-2 scatter (both scales folded) into acc2[n][f]
    scatter2_kernel<<<(RR * EE * 32 + 255) / 256, 256>>>(ei);
    // 8. per-node u/v (fused h2 epilogue: +bias, /3, relu, dot Wlin)
    uv_kernel<<<(NN * 32 + 255) / 256, 256>>>(Wlin);
    // 9. pair outputs
    pairs_kernel<<<(NPAIRS + 255) / 256, 256>>>(ei, np, blin, out);
}

// round 4
// speedup vs baseline: 3.3173x; 1.1564x over previous
#include <cuda_runtime.h>
#include <math.h>

// Problem constants (fixed shapes)
#define NN 50000
#define EE 200000
#define RR 3
#define FF 128
#define HH 256
#define PP 100000
#define NPAIRS (RR*EE + PP)   // 700000
#define NBINS (RR*NN)         // 150000

// scratch layout (floats) — [zeroed region | persistent-per-run region]
#define OFF_SC_OUT 0ull                 // 150000 (counts -> rsqrt)
#define OFF_SC_IN  150000ull            // 150000 (counts -> rsqrt)
#define OFF_CURSOR 300000ull            // 150016 ints (zeroed; == bin count after place)
#define ZERO_FLOATS 450016ull
#define OFF_OFFSET 450016ull            // 150016 ints (exclusive prefix of in-degree)
#define OFF_BLKSUM 600032ull            // 256 ints
#define OFF_ESRC   600288ull            // 600000 ints
#define OFF_ESCALE 1200288ull           // 600000 floats
#define OFF_AGG    1800288ull           // [N][R*F] = 19,200,000 ; reused as z2
#define OFF_H1     21000288ull          // [N][H]   = 12,800,000
#define OFF_ACC2   33800288ull          // [N][F]   =  6,400,000
#define OFF_U      40200288ull
#define OFF_V      40250288ull
#define OFF_BS1    40300288ull          // 256
#define OFF_BS2    40300544ull          // 128
#define OFF_W2P    40300672ull          // [H][R*F] = 98304
#define SCRATCH_TOTAL 40398976ull

__device__ float g_scratch[SCRATCH_TOTAL];

// ---------------------------------------------------------------- zero (scales + cursors only)
__global__ void zero_kernel() {
    size_t i = (size_t)blockIdx.x * blockDim.x + threadIdx.x;
    if (i < ZERO_FLOATS / 4) {
        reinterpret_cast<float4*>(g_scratch)[i] = make_float4(0.f, 0.f, 0.f, 0.f);
    }
}

// ---------------------------------------------------------------- bias sums
__global__ void bias_kernel(const float* __restrict__ b1, const float* __restrict__ b2) {
    int t = blockIdx.x * blockDim.x + threadIdx.x;
    if (t < HH) {
        g_scratch[OFF_BS1 + t] = b1[t] + b1[HH + t] + b1[2 * HH + t];
    } else if (t < HH + FF) {
        int h = t - HH;
        g_scratch[OFF_BS2 + h] = b2[h] + b2[FF + h] + b2[2 * FF + h];
    }
}

// ---------------------------------------------------------------- W2 pack: W2[r][h][f] -> W2P[h][r*F+f]
__global__ void w2pack_kernel(const float* __restrict__ W2) {
    int i = blockIdx.x * blockDim.x + threadIdx.x;
    if (i >= RR * HH * FF) return;
    int r = i / (HH * FF);
    int rem = i - r * (HH * FF);
    int h = rem / FF;
    int f = rem - h * FF;
    g_scratch[OFF_W2P + (size_t)h * (RR * FF) + r * FF + f] = W2[i];
}

// ---------------------------------------------------------------- degrees (float counts)
__global__ void deg_kernel(const int* __restrict__ ei) {
    int i = blockIdx.x * blockDim.x + threadIdx.x;
    if (i >= RR * EE) return;
    int r = i / EE, e = i - r * EE;
    int src = ei[(size_t)r * 2 * EE + e];
    int dst = ei[(size_t)r * 2 * EE + EE + e];
    atomicAdd(&g_scratch[OFF_SC_OUT + (size_t)r * NN + src], 1.f);
    atomicAdd(&g_scratch[OFF_SC_IN  + (size_t)r * NN + dst], 1.f);
}

// ---------------------------------------------------------------- prefix scan of in-degrees (3 passes)
#define SCAN_B 1024
#define SCAN_NBLK ((NBINS + SCAN_B - 1) / SCAN_B)   // 147

__global__ void scanA_kernel() {
    __shared__ int sm[SCAN_B];
    int tid = threadIdx.x;
    int i = blockIdx.x * SCAN_B + tid;
    int v = (i < NBINS) ? (int)g_scratch[OFF_SC_IN + i] : 0;
    sm[tid] = v;
    __syncthreads();
    for (int off = 1; off < SCAN_B; off <<= 1) {
        int t = (tid >= off) ? sm[tid - off] : 0;
        __syncthreads();
        sm[tid] += t;
        __syncthreads();
    }
    if (i < NBINS)
        reinterpret_cast<int*>(g_scratch)[OFF_OFFSET + i] = sm[tid] - v;   // exclusive
    if (tid == SCAN_B - 1)
        reinterpret_cast<int*>(g_scratch)[OFF_BLKSUM + blockIdx.x] = sm[tid];
}

__global__ void scanB_kernel() {
    __shared__ int sm[256];
    int tid = threadIdx.x;
    int* bs = reinterpret_cast<int*>(g_scratch) + OFF_BLKSUM;
    int v = (tid < SCAN_NBLK) ? bs[tid] : 0;
    sm[tid] = v;
    __syncthreads();
    for (int off = 1; off < 256; off <<= 1) {
        int t = (tid >= off) ? sm[tid - off] : 0;
        __syncthreads();
        sm[tid] += t;
        __syncthreads();
    }
    if (tid < SCAN_NBLK) bs[tid] = sm[tid] - v;   // exclusive block offsets
}

__global__ void scanC_kernel() {
    int i = blockIdx.x * blockDim.x + threadIdx.x;
    if (i >= NBINS) return;
    int* ip = reinterpret_cast<int*>(g_scratch);
    ip[OFF_OFFSET + i] += ip[OFF_BLKSUM + i / SCAN_B];
}

// ---------------------------------------------------------------- rsqrt of clamped degrees
__global__ void rsq_kernel() {
    int i = blockIdx.x * blockDim.x + threadIdx.x;
    if (i < 2 * NBINS) {
        float v = g_scratch[i];
        g_scratch[i] = rsqrtf(fmaxf(v, 1.f));
    }
}

// ---------------------------------------------------------------- edge placement (CSR by dst, scale folded)
__global__ void place_kernel(const int* __restrict__ ei) {
    int i = blockIdx.x * blockDim.x + threadIdx.x;
    if (i >= RR * EE) return;
    int r = i / EE, e = i - r * EE;
    int src = ei[(size_t)r * 2 * EE + e];
    int dst = ei[(size_t)r * 2 * EE + EE + e];
    float s = g_scratch[OFF_SC_OUT + (size_t)r * NN + src]
            * g_scratch[OFF_SC_IN  + (size_t)r * NN + dst];
    int bin = r * NN + dst;
    int* ip = reinterpret_cast<int*>(g_scratch);
    int pos = ip[OFF_OFFSET + bin] + atomicAdd(&ip[OFF_CURSOR + bin], 1);
    ip[OFF_ESRC + pos] = src;
    g_scratch[OFF_ESCALE + pos] = s;
}

// ---------------------------------------------------------------- gather layer 1 (warp per dst)
__global__ void gather1_kernel(const float* __restrict__ x) {
    int dst = (blockIdx.x * blockDim.x + threadIdx.x) >> 5;
    int lane = threadIdx.x & 31;
    if (dst >= NN) return;
    const int* ip = reinterpret_cast<const int*>(g_scratch);
    const float4* x4 = reinterpret_cast<const float4*>(x);
    float4* agg4 = reinterpret_cast<float4*>(&g_scratch[OFF_AGG]);
    #pragma unroll
    for (int r = 0; r < RR; r++) {
        int bin = r * NN + dst;
        int st = ip[OFF_OFFSET + bin];
        int cnt = ip[OFF_CURSOR + bin];
        float4 acc = make_float4(0.f, 0.f, 0.f, 0.f);
        for (int p = 0; p < cnt; p++) {
            int src = ip[OFF_ESRC + st + p];
            float s = g_scratch[OFF_ESCALE + st + p];
            float4 v = x4[(size_t)src * 32 + lane];
            acc.x = fmaf(s, v.x, acc.x);
            acc.y = fmaf(s, v.y, acc.y);
            acc.z = fmaf(s, v.z, acc.z);
            acc.w = fmaf(s, v.w, acc.w);
        }
        agg4[(size_t)dst * 96 + r * 32 + lane] = acc;
    }
}

// ---------------------------------------------------------------- gather layer 2 (warp per dst, sum relations)
__global__ void gather2_kernel() {
    int dst = (blockIdx.x * blockDim.x + threadIdx.x) >> 5;
    int lane = threadIdx.x & 31;
    if (dst >= NN) return;
    const int* ip = reinterpret_cast<const int*>(g_scratch);
    const float4* z4 = reinterpret_cast<const float4*>(&g_scratch[OFF_AGG]);
    float4 acc = make_float4(0.f, 0.f, 0.f, 0.f);
    #pragma unroll
    for (int r = 0; r < RR; r++) {
        int bin = r * NN + dst;
        int st = ip[OFF_OFFSET + bin];
        int cnt = ip[OFF_CURSOR + bin];
        for (int p = 0; p < cnt; p++) {
            int src = ip[OFF_ESRC + st + p];
            float s = g_scratch[OFF_ESCALE + st + p];
            float4 v = z4[(size_t)src * 96 + r * 32 + lane];
            acc.x = fmaf(s, v.x, acc.x);
            acc.y = fmaf(s, v.y, acc.y);
            acc.z = fmaf(s, v.z, acc.z);
            acc.w = fmaf(s, v.w, acc.w);
        }
    }
    reinterpret_cast<float4*>(&g_scratch[OFF_ACC2])[(size_t)dst * 32 + lane] = acc;
}

// ---------------------------------------------------------------- tf32 tensor-core GEMM
#define BM 128
#define BN 64
#define BK 16
#define APAD 8
#define BPAD 8

__device__ __forceinline__ unsigned f2tf32(float f) {
    unsigned u;
    asm("cvt.rna.tf32.f32 %0, %1;" : "=r"(u) : "f"(f));
    return u;
}

__device__ __forceinline__ void mma_tf32(float* d, const unsigned* a, const unsigned* b) {
    asm volatile("mma.sync.aligned.m16n8k8.row.col.f32.tf32.tf32.f32 "
                 "{%0,%1,%2,%3}, {%4,%5,%6,%7}, {%8,%9}, {%0,%1,%2,%3};"
                 : "+f"(d[0]), "+f"(d[1]), "+f"(d[2]), "+f"(d[3])
                 : "r"(a[0]), "r"(a[1]), "r"(a[2]), "r"(a[3]),
                   "r"(b[0]), "r"(b[1]));
}

__global__ __launch_bounds__(256) void gemm_tc_kernel(
    const float* __restrict__ A, const float* __restrict__ B,
    const float* __restrict__ bias, float* __restrict__ C,
    int M, int K, int Ncol, int doRelu, float scale)
{
    __shared__ float As[BK][BM + APAD];   // k-major
    __shared__ float Bs[BK][BN + BPAD];   // k-major

    int tid = threadIdx.x;
    int warp = tid >> 5;
    int lane = tid & 31;
    int wr = warp >> 1;
    int wc = warp & 1;
    int bm = blockIdx.y * BM, bn = blockIdx.x * BN;

    int tg = lane >> 2;
    int tq = lane & 3;

    float acc[2][4][4];
    #pragma unroll
    for (int i = 0; i < 2; i++)
        #pragma unroll
        for (int j = 0; j < 4; j++)
            #pragma unroll
            for (int q = 0; q < 4; q++) acc[i][j][q] = 0.f;

    int a_m = tid >> 2;
    int a_k4 = tid & 3;
    int b_k = tid >> 4;
    int b_n4 = tid & 15;

    for (int k0 = 0; k0 < K; k0 += BK) {
        #pragma unroll
        for (int p = 0; p < 2; p++) {
            int m = bm + p * 64 + a_m;
            float4 a = make_float4(0.f, 0.f, 0.f, 0.f);
            if (m < M) a = *reinterpret_cast<const float4*>(A + (size_t)m * K + k0 + a_k4 * 4);
            As[a_k4 * 4 + 0][p * 64 + a_m] = a.x;
            As[a_k4 * 4 + 1][p * 64 + a_m] = a.y;
            As[a_k4 * 4 + 2][p * 64 + a_m] = a.z;
            As[a_k4 * 4 + 3][p * 64 + a_m] = a.w;
        }
        {
            float4 b = *reinterpret_cast<const float4*>(B + (size_t)(k0 + b_k) * Ncol + bn + b_n4 * 4);
            Bs[b_k][b_n4 * 4 + 0] = b.x;
            Bs[b_k][b_n4 * 4 + 1] = b.y;
            Bs[b_k][b_n4 * 4 + 2] = b.z;
            Bs[b_k][b_n4 * 4 + 3] = b.w;
        }
        __syncthreads();

        #pragma unroll
        for (int kk = 0; kk < BK; kk += 8) {
            unsigned af[2][4], bf[4][2];
            #pragma unroll
            for (int i = 0; i < 2; i++) {
                int mb = wr * 32 + i * 16;
                af[i][0] = f2tf32(As[kk + tq    ][mb + tg    ]);
                af[i][1] = f2tf32(As[kk + tq    ][mb + tg + 8]);
                af[i][2] = f2tf32(As[kk + tq + 4][mb + tg    ]);
                af[i][3] = f2tf32(As[kk + tq + 4][mb + tg + 8]);
            }
            #pragma unroll
            for (int j = 0; j < 4; j++) {
                int nb = wc * 32 + j * 8;
                bf[j][0] = f2tf32(Bs[kk + tq    ][nb + tg]);
                bf[j][1] = f2tf32(Bs[kk + tq + 4][nb + tg]);
            }
            #pragma unroll
            for (int i = 0; i < 2; i++)
                #pragma unroll
                for (int j = 0; j < 4; j++)
                    mma_tf32(acc[i][j], af[i], bf[j]);
        }
        __syncthreads();
    }

    #pragma unroll
    for (int i = 0; i < 2; i++) {
        #pragma unroll
        for (int j = 0; j < 4; j++) {
            int col = bn + wc * 32 + j * 8 + tq * 2;
            float b0 = 0.f, b1 = 0.f;
            if (bias) { b0 = bias[col]; b1 = bias[col + 1]; }
            #pragma unroll
            for (int h = 0; h < 2; h++) {
                int row = bm + wr * 32 + i * 16 + tg + h * 8;
                if (row < M) {
                    float o0 = (acc[i][j][2 * h + 0] + b0) * scale;
                    float o1 = (acc[i][j][2 * h + 1] + b1) * scale;
                    if (doRelu) { o0 = fmaxf(o0, 0.f); o1 = fmaxf(o1, 0.f); }
                    *reinterpret_cast<float2*>(C + (size_t)row * Ncol + col) = make_float2(o0, o1);
                }
            }
        }
    }
}

// ---------------------------------------------------------------- per-node u/v (fused h2 epilogue)
__global__ void uv_kernel(const float* __restrict__ Wlin) {
    int w = (blockIdx.x * blockDim.x + threadIdx.x) >> 5;
    int lane = threadIdx.x & 31;
    if (w >= NN) return;
    const float inv3 = (1.f / 3.f);
    const float4* av = reinterpret_cast<const float4*>(&g_scratch[OFF_ACC2]);
    float4 h = av[(size_t)w * 32 + lane];
    float4 bb = *reinterpret_cast<const float4*>(&g_scratch[OFF_BS2 + lane * 4]);
    h.x = fmaxf((h.x + bb.x) * inv3, 0.f);
    h.y = fmaxf((h.y + bb.y) * inv3, 0.f);
    h.z = fmaxf((h.z + bb.z) * inv3, 0.f);
    h.w = fmaxf((h.w + bb.w) * inv3, 0.f);
    const float4* wv = reinterpret_cast<const float4*>(Wlin);
    float4 wl = wv[lane];
    float4 wh = wv[32 + lane];
    float su = h.x * wl.x + h.y * wl.y + h.z * wl.z + h.w * wl.w;
    float sv = h.x * wh.x + h.y * wh.y + h.z * wh.z + h.w * wh.w;
    #pragma unroll
    for (int o = 16; o > 0; o >>= 1) {
        su += __shfl_down_sync(0xffffffffu, su, o);
        sv += __shfl_down_sync(0xffffffffu, sv, o);
    }
    if (lane == 0) {
        g_scratch[OFF_U + w] = su;
        g_scratch[OFF_V + w] = sv;
    }
}

// ---------------------------------------------------------------- pair head
__global__ void pairs_kernel(const int* __restrict__ ei, const int* __restrict__ np,
                             const float* __restrict__ blin, float* __restrict__ out) {
    int i = blockIdx.x * blockDim.x + threadIdx.x;
    if (i >= NPAIRS) return;
    int src, dst;
    if (i < RR * EE) {
        int r = i / EE, e = i - r * EE;
        src = ei[(size_t)r * 2 * EE + e];
        dst = ei[(size_t)r * 2 * EE + EE + e];
    } else {
        int j = i - RR * EE;
        src = np[2 * j];
        dst = np[2 * j + 1];
    }
    float z = g_scratch[OFF_U + src] + g_scratch[OFF_V + dst] + blin[0];
    out[i] = 1.f / (1.f + expf(-z));
}

// ---------------------------------------------------------------- launch
extern "C" void kernel_launch(void* const* d_in, const int* in_sizes, int n_in,
                              void* d_out, int out_size) {
    const float* x    = (const float*)d_in[0];
    const int*   ei   = (const int*)  d_in[1];
    const int*   np   = (const int*)  d_in[2];
    const float* W1   = (const float*)d_in[3];
    const float* b1   = (const float*)d_in[4];
    const float* W2   = (const float*)d_in[5];
    const float* b2   = (const float*)d_in[6];
    const float* Wlin = (const float*)d_in[7];
    const float* blin = (const float*)d_in[8];
    float* out = (float*)d_out;

    void* base = nullptr;
    cudaGetSymbolAddress(&base, g_scratch);
    float* fb = (float*)base;
    float* agg  = fb + OFF_AGG;
    float* h1   = fb + OFF_H1;
    float* bs1  = fb + OFF_BS1;
    float* w2p  = fb + OFF_W2P;

    // 1. zero scales + cursors
    zero_kernel<<<(unsigned)((ZERO_FLOATS / 4 + 255) / 256), 256>>>();
    // 2. bias sums + W2 pack
    bias_kernel<<<2, 256>>>(b1, b2);
    w2pack_kernel<<<(RR * HH * FF + 255) / 256, 256>>>(W2);
    // 3. degrees (float counts)
    deg_kernel<<<(RR * EE + 255) / 256, 256>>>(ei);
    // 4. CSR offsets: exclusive scan of in-degrees
    scanA_kernel<<<SCAN_NBLK, SCAN_B>>>();
    scanB_kernel<<<1, 256>>>();
    scanC_kernel<<<(NBINS + 255) / 256, 256>>>();
    // 5. rsqrt scales
    rsq_kernel<<<(2 * NBINS + 255) / 256, 256>>>();
    // 6. edge placement (esrc + folded scale)
    place_kernel<<<(RR * EE + 255) / 256, 256>>>(ei);
    // 7. layer-1 gather into agg[n][r*F+f]
    gather1_kernel<<<(NN * 32 + 255) / 256, 256>>>(x);
    // 8. GEMM1: h1 = relu((agg @ W1flat + bs1)/3)
    gemm_tc_kernel<<<dim3(HH / BN, (NN + BM - 1) / BM), 256>>>(agg, W1, bs1, h1, NN, RR * FF, HH, 1, 1.f / 3.f);
    // 9. GEMM2a: z = h1 @ W2P -> reuse agg
    gemm_tc_kernel<<<dim3((RR * FF) / BN, (NN + BM - 1) / BM), 256>>>(h1, w2p, nullptr, agg, NN, HH, RR * FF, 0, 1.f);
    // 10. layer-2 gather into acc2[n][f]
    gather2_kernel<<<(NN * 32 + 255) / 256, 256>>>();
    // 11. per-node u/v
    uv_kernel<<<(NN * 32 + 255) / 256, 256>>>(Wlin);
    // 12. pair outputs
    pairs_kernel<<<(NPAIRS + 255) / 256, 256>>>(ei, np, blin, out);
}

// round 5
// speedup vs baseline: 3.3745x; 1.0173x over previous
#include <cuda_runtime.h>
#include <math.h>

// Problem constants (fixed shapes)
#define NN 50000
#define EE 200000
#define RR 3
#define FF 128
#define HH 256
#define PP 100000
#define NPAIRS (RR*EE + PP)   // 700000
#define NBINS (RR*NN)         // 150000

// scratch layout (floats) — [zeroed region | persistent-per-run region]
#define OFF_SC_OUT 0ull                 // 150000 (counts -> rsqrt)
#define OFF_SC_IN  150000ull            // 150000 (counts -> rsqrt)
#define OFF_CURSOR 300000ull            // 150016 ints (zeroed; == bin count after place)
#define ZERO_FLOATS 450016ull
#define OFF_OFFSET 450016ull            // 150016 ints (exclusive prefix of in-degree)
#define OFF_BLKSUM 600032ull            // 256 ints
#define OFF_ESRC   600288ull            // 600000 ints
#define OFF_ESCALE 1200288ull           // 600000 floats
#define OFF_AGG    1800288ull           // [N][R*F] = 19,200,000 ; reused as z2
#define OFF_H1     21000288ull          // [N][H]   = 12,800,000
#define OFF_U      33800288ull
#define OFF_V      33850288ull
#define OFF_BS1    33900288ull          // 256
#define OFF_BS2    33900544ull          // 128
#define OFF_W2P    33900672ull          // [H][R*F] = 98304
#define SCRATCH_TOTAL 33998976ull

__device__ float g_scratch[SCRATCH_TOTAL];

// ---------------------------------------------------------------- zero (scales + cursors only)
__global__ void zero_kernel() {
    size_t i = (size_t)blockIdx.x * blockDim.x + threadIdx.x;
    if (i < ZERO_FLOATS / 4) {
        reinterpret_cast<float4*>(g_scratch)[i] = make_float4(0.f, 0.f, 0.f, 0.f);
    }
}

// ---------------------------------------------------------------- bias sums
__global__ void bias_kernel(const float* __restrict__ b1, const float* __restrict__ b2) {
    int t = blockIdx.x * blockDim.x + threadIdx.x;
    if (t < HH) {
        g_scratch[OFF_BS1 + t] = b1[t] + b1[HH + t] + b1[2 * HH + t];
    } else if (t < HH + FF) {
        int h = t - HH;
        g_scratch[OFF_BS2 + h] = b2[h] + b2[FF + h] + b2[2 * FF + h];
    }
}

// ---------------------------------------------------------------- W2 pack: W2[r][h][f] -> W2P[h][r*F+f]
__global__ void w2pack_kernel(const float* __restrict__ W2) {
    int i = blockIdx.x * blockDim.x + threadIdx.x;
    if (i >= RR * HH * FF) return;
    int r = i / (HH * FF);
    int rem = i - r * (HH * FF);
    int h = rem / FF;
    int f = rem - h * FF;
    g_scratch[OFF_W2P + (size_t)h * (RR * FF) + r * FF + f] = W2[i];
}

// ---------------------------------------------------------------- degrees (float counts)
__global__ void deg_kernel(const int* __restrict__ ei) {
    int i = blockIdx.x * blockDim.x + threadIdx.x;
    if (i >= RR * EE) return;
    int r = i / EE, e = i - r * EE;
    int src = ei[(size_t)r * 2 * EE + e];
    int dst = ei[(size_t)r * 2 * EE + EE + e];
    atomicAdd(&g_scratch[OFF_SC_OUT + (size_t)r * NN + src], 1.f);
    atomicAdd(&g_scratch[OFF_SC_IN  + (size_t)r * NN + dst], 1.f);
}

// ---------------------------------------------------------------- prefix scan of in-degrees (3 passes)
#define SCAN_B 1024
#define SCAN_NBLK ((NBINS + SCAN_B - 1) / SCAN_B)   // 147

__global__ void scanA_kernel() {
    __shared__ int sm[SCAN_B];
    int tid = threadIdx.x;
    int i = blockIdx.x * SCAN_B + tid;
    int v = (i < NBINS) ? (int)g_scratch[OFF_SC_IN + i] : 0;
    sm[tid] = v;
    __syncthreads();
    for (int off = 1; off < SCAN_B; off <<= 1) {
        int t = (tid >= off) ? sm[tid - off] : 0;
        __syncthreads();
        sm[tid] += t;
        __syncthreads();
    }
    if (i < NBINS)
        reinterpret_cast<int*>(g_scratch)[OFF_OFFSET + i] = sm[tid] - v;   // exclusive
    if (tid == SCAN_B - 1)
        reinterpret_cast<int*>(g_scratch)[OFF_BLKSUM + blockIdx.x] = sm[tid];
}

__global__ void scanB_kernel() {
    __shared__ int sm[256];
    int tid = threadIdx.x;
    int* bs = reinterpret_cast<int*>(g_scratch) + OFF_BLKSUM;
    int v = (tid < SCAN_NBLK) ? bs[tid] : 0;
    sm[tid] = v;
    __syncthreads();
    for (int off = 1; off < 256; off <<= 1) {
        int t = (tid >= off) ? sm[tid - off] : 0;
        __syncthreads();
        sm[tid] += t;
        __syncthreads();
    }
    if (tid < SCAN_NBLK) bs[tid] = sm[tid] - v;   // exclusive block offsets
}

__global__ void scanC_kernel() {
    int i = blockIdx.x * blockDim.x + threadIdx.x;
    if (i >= NBINS) return;
    int* ip = reinterpret_cast<int*>(g_scratch);
    ip[OFF_OFFSET + i] += ip[OFF_BLKSUM + i / SCAN_B];
}

// ---------------------------------------------------------------- rsqrt of clamped degrees
__global__ void rsq_kernel() {
    int i = blockIdx.x * blockDim.x + threadIdx.x;
    if (i < 2 * NBINS) {
        float v = g_scratch[i];
        g_scratch[i] = rsqrtf(fmaxf(v, 1.f));
    }
}

// ---------------------------------------------------------------- edge placement (CSR by dst, scale folded)
__global__ void place_kernel(const int* __restrict__ ei) {
    int i = blockIdx.x * blockDim.x + threadIdx.x;
    if (i >= RR * EE) return;
    int r = i / EE, e = i - r * EE;
    int src = ei[(size_t)r * 2 * EE + e];
    int dst = ei[(size_t)r * 2 * EE + EE + e];
    float s = g_scratch[OFF_SC_OUT + (size_t)r * NN + src]
            * g_scratch[OFF_SC_IN  + (size_t)r * NN + dst];
    int bin = r * NN + dst;
    int* ip = reinterpret_cast<int*>(g_scratch);
    int pos = ip[OFF_OFFSET + bin] + atomicAdd(&ip[OFF_CURSOR + bin], 1);
    ip[OFF_ESRC + pos] = src;
    g_scratch[OFF_ESCALE + pos] = s;
}

// ---------------------------------------------------------------- gather layer 1 (warp per dst)
__global__ void gather1_kernel(const float* __restrict__ x) {
    int dst = (blockIdx.x * blockDim.x + threadIdx.x) >> 5;
    int lane = threadIdx.x & 31;
    if (dst >= NN) return;
    const int* ip = reinterpret_cast<const int*>(g_scratch);
    const float4* x4 = reinterpret_cast<const float4*>(x);
    float4* agg4 = reinterpret_cast<float4*>(&g_scratch[OFF_AGG]);
    #pragma unroll
    for (int r = 0; r < RR; r++) {
        int bin = r * NN + dst;
        int st = ip[OFF_OFFSET + bin];
        int cnt = ip[OFF_CURSOR + bin];
        float4 a0 = make_float4(0.f, 0.f, 0.f, 0.f);
        float4 a1 = make_float4(0.f, 0.f, 0.f, 0.f);
        int p = 0;
        for (; p + 2 <= cnt; p += 2) {
            int s0 = ip[OFF_ESRC + st + p];
            int s1 = ip[OFF_ESRC + st + p + 1];
            float c0 = g_scratch[OFF_ESCALE + st + p];
            float c1 = g_scratch[OFF_ESCALE + st + p + 1];
            float4 v0 = x4[(size_t)s0 * 32 + lane];
            float4 v1 = x4[(size_t)s1 * 32 + lane];
            a0.x = fmaf(c0, v0.x, a0.x); a0.y = fmaf(c0, v0.y, a0.y);
            a0.z = fmaf(c0, v0.z, a0.z); a0.w = fmaf(c0, v0.w, a0.w);
            a1.x = fmaf(c1, v1.x, a1.x); a1.y = fmaf(c1, v1.y, a1.y);
            a1.z = fmaf(c1, v1.z, a1.z); a1.w = fmaf(c1, v1.w, a1.w);
        }
        if (p < cnt) {
            int s0 = ip[OFF_ESRC + st + p];
            float c0 = g_scratch[OFF_ESCALE + st + p];
            float4 v0 = x4[(size_t)s0 * 32 + lane];
            a0.x = fmaf(c0, v0.x, a0.x); a0.y = fmaf(c0, v0.y, a0.y);
            a0.z = fmaf(c0, v0.z, a0.z); a0.w = fmaf(c0, v0.w, a0.w);
        }
        a0.x += a1.x; a0.y += a1.y; a0.z += a1.z; a0.w += a1.w;
        agg4[(size_t)dst * 96 + r * 32 + lane] = a0;
    }
}

// ---------------------------------------------------------------- gather layer 2 fused with uv
__global__ void gather2_uv_kernel(const float* __restrict__ Wlin) {
    int dst = (blockIdx.x * blockDim.x + threadIdx.x) >> 5;
    int lane = threadIdx.x & 31;
    if (dst >= NN) return;
    const int* ip = reinterpret_cast<const int*>(g_scratch);
    const float4* z4 = reinterpret_cast<const float4*>(&g_scratch[OFF_AGG]);
    float4 a0 = make_float4(0.f, 0.f, 0.f, 0.f);
    float4 a1 = make_float4(0.f, 0.f, 0.f, 0.f);
    #pragma unroll
    for (int r = 0; r < RR; r++) {
        int bin = r * NN + dst;
        int st = ip[OFF_OFFSET + bin];
        int cnt = ip[OFF_CURSOR + bin];
        int p = 0;
        for (; p + 2 <= cnt; p += 2) {
            int s0 = ip[OFF_ESRC + st + p];
            int s1 = ip[OFF_ESRC + st + p + 1];
            float c0 = g_scratch[OFF_ESCALE + st + p];
            float c1 = g_scratch[OFF_ESCALE + st + p + 1];
            float4 v0 = z4[(size_t)s0 * 96 + r * 32 + lane];
            float4 v1 = z4[(size_t)s1 * 96 + r * 32 + lane];
            a0.x = fmaf(c0, v0.x, a0.x); a0.y = fmaf(c0, v0.y, a0.y);
            a0.z = fmaf(c0, v0.z, a0.z); a0.w = fmaf(c0, v0.w, a0.w);
            a1.x = fmaf(c1, v1.x, a1.x); a1.y = fmaf(c1, v1.y, a1.y);
            a1.z = fmaf(c1, v1.z, a1.z); a1.w = fmaf(c1, v1.w, a1.w);
        }
        if (p < cnt) {
            int s0 = ip[OFF_ESRC + st + p];
            float c0 = g_scratch[OFF_ESCALE + st + p];
            float4 v0 = z4[(size_t)s0 * 96 + r * 32 + lane];
            a0.x = fmaf(c0, v0.x, a0.x); a0.y = fmaf(c0, v0.y, a0.y);
            a0.z = fmaf(c0, v0.z, a0.z); a0.w = fmaf(c0, v0.w, a0.w);
        }
    }
    a0.x += a1.x; a0.y += a1.y; a0.z += a1.z; a0.w += a1.w;
    // fused epilogue: +bias, /3, relu, dot with Wlin halves
    const float inv3 = (1.f / 3.f);
    float4 bb = *reinterpret_cast<const float4*>(&g_scratch[OFF_BS2 + lane * 4]);
    a0.x = fmaxf((a0.x + bb.x) * inv3, 0.f);
    a0.y = fmaxf((a0.y + bb.y) * inv3, 0.f);
    a0.z = fmaxf((a0.z + bb.z) * inv3, 0.f);
    a0.w = fmaxf((a0.w + bb.w) * inv3, 0.f);
    const float4* wv = reinterpret_cast<const float4*>(Wlin);
    float4 wl = wv[lane];
    float4 wh = wv[32 + lane];
    float su = a0.x * wl.x + a0.y * wl.y + a0.z * wl.z + a0.w * wl.w;
    float sv = a0.x * wh.x + a0.y * wh.y + a0.z * wh.z + a0.w * wh.w;
    #pragma unroll
    for (int o = 16; o > 0; o >>= 1) {
        su += __shfl_down_sync(0xffffffffu, su, o);
        sv += __shfl_down_sync(0xffffffffu, sv, o);
    }
    if (lane == 0) {
        g_scratch[OFF_U + dst] = su;
        g_scratch[OFF_V + dst] = sv;
    }
}

// ---------------------------------------------------------------- tf32 tensor-core GEMM (double-buffered, cvt at store)
#define BM 128
#define BN 64
#define BK 16
#define APAD 8
#define BPAD 8

__device__ __forceinline__ unsigned f2tf32(float f) {
    unsigned u;
    asm("cvt.rna.tf32.f32 %0, %1;" : "=r"(u) : "f"(f));
    return u;
}

__device__ __forceinline__ void mma_tf32(float* d, const unsigned* a, const unsigned* b) {
    asm volatile("mma.sync.aligned.m16n8k8.row.col.f32.tf32.tf32.f32 "
                 "{%0,%1,%2,%3}, {%4,%5,%6,%7}, {%8,%9}, {%0,%1,%2,%3};"
                 : "+f"(d[0]), "+f"(d[1]), "+f"(d[2]), "+f"(d[3])
                 : "r"(a[0]), "r"(a[1]), "r"(a[2]), "r"(a[3]),
                   "r"(b[0]), "r"(b[1]));
}

__global__ __launch_bounds__(256) void gemm_tc_kernel(
    const float* __restrict__ A, const float* __restrict__ B,
    const float* __restrict__ bias, float* __restrict__ C,
    int M, int K, int Ncol, int doRelu, float scale)
{
    __shared__ unsigned As[2][BK][BM + APAD];   // k-major, tf32 converted
    __shared__ unsigned Bs[2][BK][BN + BPAD];

    int tid = threadIdx.x;
    int warp = tid >> 5;
    int lane = tid & 31;
    int wr = warp >> 1;
    int wc = warp & 1;
    int bm = blockIdx.y * BM, bn = blockIdx.x * BN;
    int tg = lane >> 2;
    int tq = lane & 3;

    float acc[2][4][4];
    #pragma unroll
    for (int i = 0; i < 2; i++)
        #pragma unroll
        for (int j = 0; j < 4; j++)
            #pragma unroll
            for (int q = 0; q < 4; q++) acc[i][j][q] = 0.f;

    int a_m = tid >> 2;       // 0..63
    int a_k4 = tid & 3;       // float4 along K
    int b_k = tid >> 4;       // 0..15
    int b_n4 = tid & 15;      // float4 along N

    int nTiles = K / BK;

    // staging registers
    float4 aR[2], bR;

    // prologue: global load tile 0
    #pragma unroll
    for (int p = 0; p < 2; p++) {
        int m = bm + p * 64 + a_m;
        aR[p] = make_float4(0.f, 0.f, 0.f, 0.f);
        if (m < M) aR[p] = *reinterpret_cast<const float4*>(A + (size_t)m * K + a_k4 * 4);
    }
    bR = *reinterpret_cast<const float4*>(B + (size_t)b_k * Ncol + bn + b_n4 * 4);
    // store tile 0 (converted)
    #pragma unroll
    for (int p = 0; p < 2; p++) {
        As[0][a_k4 * 4 + 0][p * 64 + a_m] = f2tf32(aR[p].x);
        As[0][a_k4 * 4 + 1][p * 64 + a_m] = f2tf32(aR[p].y);
        As[0][a_k4 * 4 + 2][p * 64 + a_m] = f2tf32(aR[p].z);
        As[0][a_k4 * 4 + 3][p * 64 + a_m] = f2tf32(aR[p].w);
    }
    Bs[0][b_k][b_n4 * 4 + 0] = f2tf32(bR.x);
    Bs[0][b_k][b_n4 * 4 + 1] = f2tf32(bR.y);
    Bs[0][b_k][b_n4 * 4 + 2] = f2tf32(bR.z);
    Bs[0][b_k][b_n4 * 4 + 3] = f2tf32(bR.w);
    __syncthreads();

    for (int t = 0; t < nTiles; t++) {
        int cur = t & 1;
        int nxt = cur ^ 1;
        if (t + 1 < nTiles) {
            int k0 = (t + 1) * BK;
            #pragma unroll
            for (int p = 0; p < 2; p++) {
                int m = bm + p * 64 + a_m;
                aR[p] = make_float4(0.f, 0.f, 0.f, 0.f);
                if (m < M) aR[p] = *reinterpret_cast<const float4*>(A + (size_t)m * K + k0 + a_k4 * 4);
            }
            bR = *reinterpret_cast<const float4*>(B + (size_t)(k0 + b_k) * Ncol + bn + b_n4 * 4);
        }

        #pragma unroll
        for (int kk = 0; kk < BK; kk += 8) {
            unsigned af[2][4], bf[4][2];
            #pragma unroll
            for (int i = 0; i < 2; i++) {
                int mb = wr * 32 + i * 16;
                af[i][0] = As[cur][kk + tq    ][mb + tg    ];
                af[i][1] = As[cur][kk + tq    ][mb + tg + 8];
                af[i][2] = As[cur][kk + tq + 4][mb + tg    ];
                af[i][3] = As[cur][kk + tq + 4][mb + tg + 8];
            }
            #pragma unroll
            for (int j = 0; j < 4; j++) {
                int nb = wc * 32 + j * 8;
                bf[j][0] = Bs[cur][kk + tq    ][nb + tg];
                bf[j][1] = Bs[cur][kk + tq + 4][nb + tg];
            }
            #pragma unroll
            for (int i = 0; i < 2; i++)
                #pragma unroll
                for (int j = 0; j < 4; j++)
                    mma_tf32(acc[i][j], af[i], bf[j]);
        }

        if (t + 1 < nTiles) {
            #pragma unroll
            for (int p = 0; p < 2; p++) {
                As[nxt][a_k4 * 4 + 0][p * 64 + a_m] = f2tf32(aR[p].x);
                As[nxt][a_k4 * 4 + 1][p * 64 + a_m] = f2tf32(aR[p].y);
                As[nxt][a_k4 * 4 + 2][p * 64 + a_m] = f2tf32(aR[p].z);
                As[nxt][a_k4 * 4 + 3][p * 64 + a_m] = f2tf32(aR[p].w);
            }
            Bs[nxt][b_k][b_n4 * 4 + 0] = f2tf32(bR.x);
            Bs[nxt][b_k][b_n4 * 4 + 1] = f2tf32(bR.y);
            Bs[nxt][b_k][b_n4 * 4 + 2] = f2tf32(bR.z);
            Bs[nxt][b_k][b_n4 * 4 + 3] = f2tf32(bR.w);
            __syncthreads();
        }
    }

    #pragma unroll
    for (int i = 0; i < 2; i++) {
        #pragma unroll
        for (int j = 0; j < 4; j++) {
            int col = bn + wc * 32 + j * 8 + tq * 2;
            float b0 = 0.f, b1 = 0.f;
            if (bias) { b0 = bias[col]; b1 = bias[col + 1]; }
            #pragma unroll
            for (int h = 0; h < 2; h++) {
                int row = bm + wr * 32 + i * 16 + tg + h * 8;
                if (row < M) {
                    float o0 = (acc[i][j][2 * h + 0] + b0) * scale;
                    float o1 = (acc[i][j][2 * h + 1] + b1) * scale;
                    if (doRelu) { o0 = fmaxf(o0, 0.f); o1 = fmaxf(o1, 0.f); }
                    *reinterpret_cast<float2*>(C + (size_t)row * Ncol + col) = make_float2(o0, o1);
                }
            }
        }
    }
}

// ---------------------------------------------------------------- pair head
__global__ void pairs_kernel(const int* __restrict__ ei, const int* __restrict__ np,
                             const float* __restrict__ blin, float* __restrict__ out) {
    int i = blockIdx.x * blockDim.x + threadIdx.x;
    if (i >= NPAIRS) return;
    int src, dst;
    if (i < RR * EE) {
        int r = i / EE, e = i - r * EE;
        src = ei[(size_t)r * 2 * EE + e];
        dst = ei[(size_t)r * 2 * EE + EE + e];
    } else {
        int j = i - RR * EE;
        src = np[2 * j];
        dst = np[2 * j + 1];
    }
    float z = g_scratch[OFF_U + src] + g_scratch[OFF_V + dst] + blin[0];
    out[i] = 1.f / (1.f + expf(-z));
}

// ---------------------------------------------------------------- launch
extern "C" void kernel_launch(void* const* d_in, const int* in_sizes, int n_in,
                              void* d_out, int out_size) {
    const float* x    = (const float*)d_in[0];
    const int*   ei   = (const int*)  d_in[1];
    const int*   np   = (const int*)  d_in[2];
    const float* W1   = (const float*)d_in[3];
    const float* b1   = (const float*)d_in[4];
    const float* W2   = (const float*)d_in[5];
    const float* b2   = (const float*)d_in[6];
    const float* Wlin = (const float*)d_in[7];
    const float* blin = (const float*)d_in[8];
    float* out = (float*)d_out;

    void* base = nullptr;
    cudaGetSymbolAddress(&base, g_scratch);
    float* fb = (float*)base;
    float* agg  = fb + OFF_AGG;
    float* h1   = fb + OFF_H1;
    float* bs1  = fb + OFF_BS1;
    float* w2p  = fb + OFF_W2P;

    // 1. zero scales + cursors
    zero_kernel<<<(unsigned)((ZERO_FLOATS / 4 + 255) / 256), 256>>>();
    // 2. bias sums + W2 pack
    bias_kernel<<<2, 256>>>(b1, b2);
    w2pack_kernel<<<(RR * HH * FF + 255) / 256, 256>>>(W2);
    // 3. degrees (float counts)
    deg_kernel<<<(RR * EE + 255) / 256, 256>>>(ei);
    // 4. CSR offsets: exclusive scan of in-degrees
    scanA_kernel<<<SCAN_NBLK, SCAN_B>>>();
    scanB_kernel<<<1, 256>>>();
    scanC_kernel<<<(NBINS + 255) / 256, 256>>>();
    // 5. rsqrt scales
    rsq_kernel<<<(2 * NBINS + 255) / 256, 256>>>();
    // 6. edge placement (esrc + folded scale)
    place_kernel<<<(RR * EE + 255) / 256, 256>>>(ei);
    // 7. layer-1 gather into agg[n][r*F+f]
    gather1_kernel<<<(NN * 32 + 255) / 256, 256>>>(x);
    // 8. GEMM1: h1 = relu((agg @ W1flat + bs1)/3)
    gemm_tc_kernel<<<dim3(HH / BN, (NN + BM - 1) / BM), 256>>>(agg, W1, bs1, h1, NN, RR * FF, HH, 1, 1.f / 3.f);
    // 9. GEMM2a: z = h1 @ W2P -> reuse agg
    gemm_tc_kernel<<<dim3((RR * FF) / BN, (NN + BM - 1) / BM), 256>>>(h1, w2p, nullptr, agg, NN, HH, RR * FF, 0, 1.f);
    // 10. layer-2 gather fused with u/v epilogue
    gather2_uv_kernel<<<(NN * 32 + 255) / 256, 256>>>(Wlin);
    // 11. pair outputs
    pairs_kernel<<<(NPAIRS + 255) / 256, 256>>>(ei, np, blin, out);
}

// round 7
// speedup vs baseline: 5.2414x; 1.5533x over previous
#include <cuda_runtime.h>
#include <cuda_fp16.h>
#include <math.h>
#include <stdint.h>

// Problem constants (fixed shapes)
#define NN 50000
#define EE 200000
#define RR 3
#define FF 128
#define HH 256
#define PP 100000
#define NPAIRS (RR*EE + PP)   // 700000
#define NBINS (RR*NN)         // 150000

// scratch layout (float slots) — [zeroed region | persistent region]
#define OFF_SC_OUT 0ull                 // 150000
#define OFF_SC_IN  150000ull            // 150000
#define OFF_CURSOR 300000ull            // 150016 ints
#define ZERO_FLOATS 450016ull
#define OFF_OFFSET 450016ull            // 150016 ints
#define OFF_BLKSUM 600032ull            // 256 ints
#define OFF_ESRC   600288ull            // 600000 ints
#define OFF_ESCALE 1200288ull           // 600000 floats
#define OFF_AGGH   1800288ull           // half[N][384] = 9,600,000 float slots ; reused as z
#define OFF_H1H    11400288ull          // half[N][256] = 6,400,000 float slots
#define OFF_U      17800288ull
#define OFF_V      17850288ull
#define OFF_BS1    17900288ull          // 256 floats
#define OFF_BS2    17900544ull          // 128 floats
#define OFF_BT1H   17900672ull          // half[256][384] = 49152 float slots
#define OFF_BT2H   17949824ull          // half[384][256] = 49152 float slots
#define SCRATCH_TOTAL 17998976ull

__device__ float g_scratch[SCRATCH_TOTAL];

// ================================================================ small kernels
__global__ void zero_kernel() {
    size_t i = (size_t)blockIdx.x * blockDim.x + threadIdx.x;
    if (i < ZERO_FLOATS / 4)
        reinterpret_cast<float4*>(g_scratch)[i] = make_float4(0.f, 0.f, 0.f, 0.f);
}

__global__ void bias_kernel(const float* __restrict__ b1, const float* __restrict__ b2) {
    int t = blockIdx.x * blockDim.x + threadIdx.x;
    if (t < HH) {
        g_scratch[OFF_BS1 + t] = b1[t] + b1[HH + t] + b1[2 * HH + t];
    } else if (t < HH + FF) {
        int h = t - HH;
        g_scratch[OFF_BS2 + h] = b2[h] + b2[FF + h] + b2[2 * FF + h];
    }
}

// Bt1h[h][k] = half(W1[k][h])  (h 0..255, k 0..383) — W1 flat row-major [384][256]
__global__ void bt1_kernel(const float* __restrict__ W1) {
    int i = blockIdx.x * blockDim.x + threadIdx.x;
    if (i >= HH * RR * FF) return;
    int h = i / (RR * FF);
    int k = i - h * (RR * FF);
    __half* bt = reinterpret_cast<__half*>(&g_scratch[OFF_BT1H]);
    bt[(size_t)h * (RR * FF) + k] = __float2half(W1[(size_t)k * HH + h]);
}

// Bt2h[rf][h] = half(W2[r][h][f]),  rf = r*F+f
__global__ void bt2_kernel(const float* __restrict__ W2) {
    int i = blockIdx.x * blockDim.x + threadIdx.x;
    if (i >= RR * FF * HH) return;
    int rf = i / HH;
    int h = i - rf * HH;
    int r = rf >> 7;
    int f = rf & 127;
    __half* bt = reinterpret_cast<__half*>(&g_scratch[OFF_BT2H]);
    bt[(size_t)rf * HH + h] = __float2half(W2[(size_t)r * HH * FF + (size_t)h * FF + f]);
}

__global__ void deg_kernel(const int* __restrict__ ei) {
    int i = blockIdx.x * blockDim.x + threadIdx.x;
    if (i >= RR * EE) return;
    int r = i / EE, e = i - r * EE;
    int src = ei[(size_t)r * 2 * EE + e];
    int dst = ei[(size_t)r * 2 * EE + EE + e];
    atomicAdd(&g_scratch[OFF_SC_OUT + (size_t)r * NN + src], 1.f);
    atomicAdd(&g_scratch[OFF_SC_IN  + (size_t)r * NN + dst], 1.f);
}

#define SCAN_B 1024
#define SCAN_NBLK ((NBINS + SCAN_B - 1) / SCAN_B)   // 147

__global__ void scanA_kernel() {
    __shared__ int sm[SCAN_B];
    int tid = threadIdx.x;
    int i = blockIdx.x * SCAN_B + tid;
    int v = (i < NBINS) ? (int)g_scratch[OFF_SC_IN + i] : 0;
    sm[tid] = v;
    __syncthreads();
    for (int off = 1; off < SCAN_B; off <<= 1) {
        int t = (tid >= off) ? sm[tid - off] : 0;
        __syncthreads();
        sm[tid] += t;
        __syncthreads();
    }
    if (i < NBINS)
        reinterpret_cast<int*>(g_scratch)[OFF_OFFSET + i] = sm[tid] - v;
    if (tid == SCAN_B - 1)
        reinterpret_cast<int*>(g_scratch)[OFF_BLKSUM + blockIdx.x] = sm[tid];
}

__global__ void scanB_kernel() {
    __shared__ int sm[256];
    int tid = threadIdx.x;
    int* bs = reinterpret_cast<int*>(g_scratch) + OFF_BLKSUM;
    int v = (tid < SCAN_NBLK) ? bs[tid] : 0;
    sm[tid] = v;
    __syncthreads();
    for (int off = 1; off < 256; off <<= 1) {
        int t = (tid >= off) ? sm[tid - off] : 0;
        __syncthreads();
        sm[tid] += t;
        __syncthreads();
    }
    if (tid < SCAN_NBLK) bs[tid] = sm[tid] - v;
}

__global__ void scanC_kernel() {
    int i = blockIdx.x * blockDim.x + threadIdx.x;
    if (i >= NBINS) return;
    int* ip = reinterpret_cast<int*>(g_scratch);
    ip[OFF_OFFSET + i] += ip[OFF_BLKSUM + i / SCAN_B];
}

__global__ void rsq_kernel() {
    int i = blockIdx.x * blockDim.x + threadIdx.x;
    if (i < 2 * NBINS) {
        float v = g_scratch[i];
        g_scratch[i] = rsqrtf(fmaxf(v, 1.f));
    }
}

__global__ void place_kernel(const int* __restrict__ ei) {
    int i = blockIdx.x * blockDim.x + threadIdx.x;
    if (i >= RR * EE) return;
    int r = i / EE, e = i - r * EE;
    int src = ei[(size_t)r * 2 * EE + e];
    int dst = ei[(size_t)r * 2 * EE + EE + e];
    float s = g_scratch[OFF_SC_OUT + (size_t)r * NN + src]
            * g_scratch[OFF_SC_IN  + (size_t)r * NN + dst];
    int bin = r * NN + dst;
    int* ip = reinterpret_cast<int*>(g_scratch);
    int pos = ip[OFF_OFFSET + bin] + atomicAdd(&ip[OFF_CURSOR + bin], 1);
    ip[OFF_ESRC + pos] = src;
    g_scratch[OFF_ESCALE + pos] = s;
}

// ================================================================ gather layer 1 (fp32 accum, half out)
__global__ void gather1_kernel(const float* __restrict__ x) {
    int dst = (blockIdx.x * blockDim.x + threadIdx.x) >> 5;
    int lane = threadIdx.x & 31;
    if (dst >= NN) return;
    const int* ip = reinterpret_cast<const int*>(g_scratch);
    const float4* x4 = reinterpret_cast<const float4*>(x);
    __half* aggh = reinterpret_cast<__half*>(&g_scratch[OFF_AGGH]);
    #pragma unroll
    for (int r = 0; r < RR; r++) {
        int bin = r * NN + dst;
        int st = ip[OFF_OFFSET + bin];
        int cnt = ip[OFF_CURSOR + bin];
        float4 a0 = make_float4(0.f, 0.f, 0.f, 0.f);
        float4 a1 = make_float4(0.f, 0.f, 0.f, 0.f);
        int p = 0;
        for (; p + 2 <= cnt; p += 2) {
            int s0 = ip[OFF_ESRC + st + p];
            int s1 = ip[OFF_ESRC + st + p + 1];
            float c0 = g_scratch[OFF_ESCALE + st + p];
            float c1 = g_scratch[OFF_ESCALE + st + p + 1];
            float4 v0 = x4[(size_t)s0 * 32 + lane];
            float4 v1 = x4[(size_t)s1 * 32 + lane];
            a0.x = fmaf(c0, v0.x, a0.x); a0.y = fmaf(c0, v0.y, a0.y);
            a0.z = fmaf(c0, v0.z, a0.z); a0.w = fmaf(c0, v0.w, a0.w);
            a1.x = fmaf(c1, v1.x, a1.x); a1.y = fmaf(c1, v1.y, a1.y);
            a1.z = fmaf(c1, v1.z, a1.z); a1.w = fmaf(c1, v1.w, a1.w);
        }
        if (p < cnt) {
            int s0 = ip[OFF_ESRC + st + p];
            float c0 = g_scratch[OFF_ESCALE + st + p];
            float4 v0 = x4[(size_t)s0 * 32 + lane];
            a0.x = fmaf(c0, v0.x, a0.x); a0.y = fmaf(c0, v0.y, a0.y);
            a0.z = fmaf(c0, v0.z, a0.z); a0.w = fmaf(c0, v0.w, a0.w);
        }
        a0.x += a1.x; a0.y += a1.y; a0.z += a1.z; a0.w += a1.w;
        __half2 h01 = __floats2half2_rn(a0.x, a0.y);
        __half2 h23 = __floats2half2_rn(a0.z, a0.w);
        uint2 st2;
        st2.x = *reinterpret_cast<unsigned*>(&h01);
        st2.y = *reinterpret_cast<unsigned*>(&h23);
        *reinterpret_cast<uint2*>(aggh + (size_t)dst * 384 + r * FF + lane * 4) = st2;
    }
}

// ================================================================ gather layer 2 (half in) fused with uv
__global__ void gather2_uv_kernel(const float* __restrict__ Wlin) {
    int dst = (blockIdx.x * blockDim.x + threadIdx.x) >> 5;
    int lane = threadIdx.x & 31;
    if (dst >= NN) return;
    const int* ip = reinterpret_cast<const int*>(g_scratch);
    const __half* zh = reinterpret_cast<const __half*>(&g_scratch[OFF_AGGH]);
    float4 a0 = make_float4(0.f, 0.f, 0.f, 0.f);
    float4 a1 = make_float4(0.f, 0.f, 0.f, 0.f);
    #pragma unroll
    for (int r = 0; r < RR; r++) {
        int bin = r * NN + dst;
        int st = ip[OFF_OFFSET + bin];
        int cnt = ip[OFF_CURSOR + bin];
        int p = 0;
        for (; p + 2 <= cnt; p += 2) {
            int s0 = ip[OFF_ESRC + st + p];
            int s1 = ip[OFF_ESRC + st + p + 1];
            float c0 = g_scratch[OFF_ESCALE + st + p];
            float c1 = g_scratch[OFF_ESCALE + st + p + 1];
            uint2 w0 = *reinterpret_cast<const uint2*>(zh + (size_t)s0 * 384 + r * FF + lane * 4);
            uint2 w1 = *reinterpret_cast<const uint2*>(zh + (size_t)s1 * 384 + r * FF + lane * 4);
            float2 f0a = __half22float2(*reinterpret_cast<__half2*>(&w0.x));
            float2 f0b = __half22float2(*reinterpret_cast<__half2*>(&w0.y));
            float2 f1a = __half22float2(*reinterpret_cast<__half2*>(&w1.x));
            float2 f1b = __half22float2(*reinterpret_cast<__half2*>(&w1.y));
            a0.x = fmaf(c0, f0a.x, a0.x); a0.y = fmaf(c0, f0a.y, a0.y);
            a0.z = fmaf(c0, f0b.x, a0.z); a0.w = fmaf(c0, f0b.y, a0.w);
            a1.x = fmaf(c1, f1a.x, a1.x); a1.y = fmaf(c1, f1a.y, a1.y);
            a1.z = fmaf(c1, f1b.x, a1.z); a1.w = fmaf(c1, f1b.y, a1.w);
        }
        if (p < cnt) {
            int s0 = ip[OFF_ESRC + st + p];
            float c0 = g_scratch[OFF_ESCALE + st + p];
            uint2 w0 = *reinterpret_cast<const uint2*>(zh + (size_t)s0 * 384 + r * FF + lane * 4);
            float2 f0a = __half22float2(*reinterpret_cast<__half2*>(&w0.x));
            float2 f0b = __half22float2(*reinterpret_cast<__half2*>(&w0.y));
            a0.x = fmaf(c0, f0a.x, a0.x); a0.y = fmaf(c0, f0a.y, a0.y);
            a0.z = fmaf(c0, f0b.x, a0.z); a0.w = fmaf(c0, f0b.y, a0.w);
        }
    }
    a0.x += a1.x; a0.y += a1.y; a0.z += a1.z; a0.w += a1.w;
    const float inv3 = (1.f / 3.f);
    float4 bb = *reinterpret_cast<const float4*>(&g_scratch[OFF_BS2 + lane * 4]);
    a0.x = fmaxf((a0.x + bb.x) * inv3, 0.f);
    a0.y = fmaxf((a0.y + bb.y) * inv3, 0.f);
    a0.z = fmaxf((a0.z + bb.z) * inv3, 0.f);
    a0.w = fmaxf((a0.w + bb.w) * inv3, 0.f);
    const float4* wv = reinterpret_cast<const float4*>(Wlin);
    float4 wl = wv[lane];
    float4 wh = wv[32 + lane];
    float su = a0.x * wl.x + a0.y * wl.y + a0.z * wl.z + a0.w * wl.w;
    float sv = a0.x * wh.x + a0.y * wh.y + a0.z * wh.z + a0.w * wh.w;
    #pragma unroll
    for (int o = 16; o > 0; o >>= 1) {
        su += __shfl_down_sync(0xffffffffu, su, o);
        sv += __shfl_down_sync(0xffffffffu, sv, o);
    }
    if (lane == 0) {
        g_scratch[OFF_U + dst] = su;
        g_scratch[OFF_V + dst] = sv;
    }
}

// ================================================================ fp16 tensor-core GEMM (m16n8k16)
// C[M,Ncol](half) = op((A[M,K](half) @ Bt^T + bias) * scale); Bt is [Ncol][K] half (n-major)
#define BM 128
#define BN 64
#define BK 32
#define BKP 40   // +8 halves pad -> conflict-free fragment loads

__device__ __forceinline__ void mma_fp16(float* d, const unsigned* a, const unsigned* b) {
    asm volatile("mma.sync.aligned.m16n8k16.row.col.f32.f16.f16.f32 "
                 "{%0,%1,%2,%3}, {%4,%5,%6,%7}, {%8,%9}, {%0,%1,%2,%3};"
                 : "+f"(d[0]), "+f"(d[1]), "+f"(d[2]), "+f"(d[3])
                 : "r"(a[0]), "r"(a[1]), "r"(a[2]), "r"(a[3]),
                   "r"(b[0]), "r"(b[1]));
}

__global__ __launch_bounds__(256) void gemm_fp16_kernel(
    const __half* __restrict__ A, const __half* __restrict__ Bt,
    const float* __restrict__ bias, __half* __restrict__ C,
    int M, int K, int Ncol, int doRelu, float scale)
{
    __shared__ __half As[BM][BKP];   // m-major
    __shared__ __half Bs[BN][BKP];   // n-major

    int tid = threadIdx.x;
    int warp = tid >> 5;
    int lane = tid & 31;
    int wr = warp >> 1;        // 0..3 -> m offset 32*wr
    int wc = warp & 1;         // 0..1 -> n offset 32*wc
    int bm = blockIdx.y * BM, bn = blockIdx.x * BN;
    int tg = lane >> 2;        // 0..7
    int tq = lane & 3;         // 0..3

    float acc[2][4][4];
    #pragma unroll
    for (int i = 0; i < 2; i++)
        #pragma unroll
        for (int j = 0; j < 4; j++)
            #pragma unroll
            for (int q = 0; q < 4; q++) acc[i][j][q] = 0.f;

    int ld_row = tid >> 2;     // 0..63
    int ld_c8 = tid & 3;       // which 8-half chunk in the 32-half row

    for (int k0 = 0; k0 < K; k0 += BK) {
        // A tile: 128 rows x 32 halves, two passes of 64 rows
        #pragma unroll
        for (int p = 0; p < 2; p++) {
            int m = bm + p * 64 + ld_row;
            uint4 v = make_uint4(0, 0, 0, 0);
            if (m < M) v = *reinterpret_cast<const uint4*>(A + (size_t)m * K + k0 + ld_c8 * 8);
            *reinterpret_cast<uint4*>(&As[p * 64 + ld_row][ld_c8 * 8]) = v;
        }
        // B tile: 64 rows (n) x 32 halves
        {
            uint4 v = *reinterpret_cast<const uint4*>(Bt + (size_t)(bn + ld_row) * K + k0 + ld_c8 * 8);
            *reinterpret_cast<uint4*>(&Bs[ld_row][ld_c8 * 8]) = v;
        }
        __syncthreads();

        #pragma unroll
        for (int kk = 0; kk < BK; kk += 16) {
            unsigned af[2][4], bf[4][2];
            #pragma unroll
            for (int i = 0; i < 2; i++) {
                int mb = wr * 32 + i * 16;
                af[i][0] = *reinterpret_cast<unsigned*>(&As[mb + tg    ][kk + 2 * tq    ]);
                af[i][1] = *reinterpret_cast<unsigned*>(&As[mb + tg + 8][kk + 2 * tq    ]);
                af[i][2] = *reinterpret_cast<unsigned*>(&As[mb + tg    ][kk + 2 * tq + 8]);
                af[i][3] = *reinterpret_cast<unsigned*>(&As[mb + tg + 8][kk + 2 * tq + 8]);
            }
            #pragma unroll
            for (int j = 0; j < 4; j++) {
                int nb = wc * 32 + j * 8;
                bf[j][0] = *reinterpret_cast<unsigned*>(&Bs[nb + tg][kk + 2 * tq    ]);
                bf[j][1] = *reinterpret_cast<unsigned*>(&Bs[nb + tg][kk + 2 * tq + 8]);
            }
            #pragma unroll
            for (int i = 0; i < 2; i++)
                #pragma unroll
                for (int j = 0; j < 4; j++)
                    mma_fp16(acc[i][j], af[i], bf[j]);
        }
        __syncthreads();
    }

    // epilogue: half2 stores
    #pragma unroll
    for (int i = 0; i < 2; i++) {
        #pragma unroll
        for (int j = 0; j < 4; j++) {
            int col = bn + wc * 32 + j * 8 + tq * 2;
            float b0 = 0.f, b1 = 0.f;
            if (bias) { b0 = bias[col]; b1 = bias[col + 1]; }
            #pragma unroll
            for (int h = 0; h < 2; h++) {
                int row = bm + wr * 32 + i * 16 + tg + h * 8;
                if (row < M) {
                    float o0 = (acc[i][j][2 * h + 0] + b0) * scale;
                    float o1 = (acc[i][j][2 * h + 1] + b1) * scale;
                    if (doRelu) { o0 = fmaxf(o0, 0.f); o1 = fmaxf(o1, 0.f); }
                    *reinterpret_cast<__half2*>(C + (size_t)row * Ncol + col) =
                        __floats2half2_rn(o0, o1);
                }
            }
        }
    }
}

// ================================================================ pair head
__global__ void pairs_kernel(const int* __restrict__ ei, const int* __restrict__ np,
                             const float* __restrict__ blin, float* __restrict__ out) {
    int i = blockIdx.x * blockDim.x + threadIdx.x;
    if (i >= NPAIRS) return;
    int src, dst;
    if (i < RR * EE) {
        int r = i / EE, e = i - r * EE;
        src = ei[(size_t)r * 2 * EE + e];
        dst = ei[(size_t)r * 2 * EE + EE + e];
    } else {
        int j = i - RR * EE;
        src = np[2 * j];
        dst = np[2 * j + 1];
    }
    float z = g_scratch[OFF_U + src] + g_scratch[OFF_V + dst] + blin[0];
    out[i] = 1.f / (1.f + expf(-z));
}

// ================================================================ launch
extern "C" void kernel_launch(void* const* d_in, const int* in_sizes, int n_in,
                              void* d_out, int out_size) {
    const float* x    = (const float*)d_in[0];
    const int*   ei   = (const int*)  d_in[1];
    const int*   np   = (const int*)  d_in[2];
    const float* W1   = (const float*)d_in[3];
    const float* b1   = (const float*)d_in[4];
    const float* W2   = (const float*)d_in[5];
    const float* b2   = (const float*)d_in[6];
    const float* Wlin = (const float*)d_in[7];
    const float* blin = (const float*)d_in[8];
    float* out = (float*)d_out;

    void* base = nullptr;
    cudaGetSymbolAddress(&base, g_scratch);
    float* fb = (float*)base;
    __half* aggh = (__half*)(fb + OFF_AGGH);
    __half* h1h  = (__half*)(fb + OFF_H1H);
    __half* bt1h = (__half*)(fb + OFF_BT1H);
    __half* bt2h = (__half*)(fb + OFF_BT2H);
    float* bs1   = fb + OFF_BS1;

    // 1. zero scales + cursors
    zero_kernel<<<(unsigned)((ZERO_FLOATS / 4 + 255) / 256), 256>>>();
    // 2. bias sums + weight packs (fp16, pre-transposed n-major)
    bias_kernel<<<2, 256>>>(b1, b2);
    bt1_kernel<<<(HH * RR * FF + 255) / 256, 256>>>(W1);
    bt2_kernel<<<(RR * FF * HH + 255) / 256, 256>>>(W2);
    // 3. degrees
    deg_kernel<<<(RR * EE + 255) / 256, 256>>>(ei);
    // 4. CSR offsets
    scanA_kernel<<<SCAN_NBLK, SCAN_B>>>();
    scanB_kernel<<<1, 256>>>();
    scanC_kernel<<<(NBINS + 255) / 256, 256>>>();
    // 5. rsqrt scales
    rsq_kernel<<<(2 * NBINS + 255) / 256, 256>>>();
    // 6. edge placement
    place_kernel<<<(RR * EE + 255) / 256, 256>>>(ei);
    // 7. layer-1 gather -> agg (half)
    gather1_kernel<<<(NN * 32 + 255) / 256, 256>>>(x);
    // 8. GEMM1: h1 = relu((agg @ W1 + bs1)/3)  [50000,384]x[384,256] fp16
    gemm_fp16_kernel<<<dim3(HH / BN, (NN + BM - 1) / BM), 256>>>(
        aggh, bt1h, bs1, h1h, NN, RR * FF, HH, 1, 1.f / 3.f);
    // 9. GEMM2: z = h1 @ W2P  [50000,256]x[256,384] fp16 -> reuse aggh
    gemm_fp16_kernel<<<dim3((RR * FF) / BN, (NN + BM - 1) / BM), 256>>>(
        h1h, bt2h, nullptr, aggh, NN, HH, RR * FF, 0, 1.f);
    // 10. layer-2 gather (half in) + u/v
    gather2_uv_kernel<<<(NN * 32 + 255) / 256, 256>>>(Wlin);
    // 11. pair outputs
    pairs_kernel<<<(NPAIRS + 255) / 256, 256>>>(ei, np, blin, out);
}

// round 8
// speedup vs baseline: 5.2777x; 1.0069x over previous
#include <cuda_runtime.h>
#include <cuda_fp16.h>
#include <math.h>
#include <stdint.h>

// Problem constants (fixed shapes)
#define NN 50000
#define EE 200000
#define RR 3
#define FF 128
#define HH 256
#define PP 100000
#define NPAIRS (RR*EE + PP)   // 700000
#define NBINS (RR*NN)         // 150000

// scratch layout (float slots) — [zeroed region | persistent region]
#define OFF_SC_OUT 0ull                 // 150000 raw out-degree counts
#define OFF_SC_IN  150000ull            // 150000 raw in-degree counts
#define OFF_CURSOR 300000ull            // 150016 ints
#define ZERO_FLOATS 450016ull
#define OFF_OFFSET 450016ull            // 150016 ints
#define OFF_BLKSUM 600032ull            // 256 ints
#define OFF_EDG    600288ull            // 600000 x uint2 {src, scale} = 1,200,000 slots
#define OFF_XH     1800288ull           // half[N][128] = 3,200,000 slots
#define OFF_AGGH   5000288ull           // half[N][384] = 9,600,000 slots ; reused as z
#define OFF_H1H    14600288ull          // half[N][256] = 6,400,000 slots
#define OFF_U      21000288ull
#define OFF_V      21050288ull
#define OFF_BS1    21100288ull          // 256 floats
#define OFF_BS2    21100544ull          // 128 floats
#define OFF_BT1H   21100672ull          // half[256][384] = 49152 slots
#define OFF_BT2H   21149824ull          // half[384][256] = 49152 slots
#define SCRATCH_TOTAL 21198976ull

__device__ float g_scratch[SCRATCH_TOTAL];

// ================================================================ small kernels
__global__ void zero_kernel() {
    size_t i = (size_t)blockIdx.x * blockDim.x + threadIdx.x;
    if (i < ZERO_FLOATS / 4)
        reinterpret_cast<float4*>(g_scratch)[i] = make_float4(0.f, 0.f, 0.f, 0.f);
}

// fused weight/bias pack:
//  [0, 98304)           : Bt1h[h][k] = half(W1[k][h])
//  [98304, 196608)      : Bt2h[rf][h] = half(W2[r][h][f])
//  [196608, 196992)     : bias sums
__global__ void pack_kernel(const float* __restrict__ W1, const float* __restrict__ W2,
                            const float* __restrict__ b1, const float* __restrict__ b2) {
    int i = blockIdx.x * blockDim.x + threadIdx.x;
    if (i < HH * RR * FF) {
        int h = i / (RR * FF);
        int k = i - h * (RR * FF);
        __half* bt = reinterpret_cast<__half*>(&g_scratch[OFF_BT1H]);
        bt[(size_t)h * (RR * FF) + k] = __float2half(W1[(size_t)k * HH + h]);
    } else if (i < 2 * HH * RR * FF) {
        int j = i - HH * RR * FF;
        int rf = j / HH;
        int h = j - rf * HH;
        int r = rf >> 7;
        int f = rf & 127;
        __half* bt = reinterpret_cast<__half*>(&g_scratch[OFF_BT2H]);
        bt[(size_t)rf * HH + h] = __float2half(W2[(size_t)r * HH * FF + (size_t)h * FF + f]);
    } else {
        int t = i - 2 * HH * RR * FF;
        if (t < HH) {
            g_scratch[OFF_BS1 + t] = b1[t] + b1[HH + t] + b1[2 * HH + t];
        } else if (t < HH + FF) {
            int h = t - HH;
            g_scratch[OFF_BS2 + h] = b2[h] + b2[FF + h] + b2[2 * FF + h];
        }
    }
}

// x (fp32) -> xh (half); 8 elements per thread
__global__ void xh_kernel(const float* __restrict__ x) {
    int i = blockIdx.x * blockDim.x + threadIdx.x;
    if (i >= NN * FF / 8) return;
    const float4* x4 = reinterpret_cast<const float4*>(x);
    float4 a = x4[2 * i];
    float4 b = x4[2 * i + 1];
    __half2 h0 = __floats2half2_rn(a.x, a.y);
    __half2 h1 = __floats2half2_rn(a.z, a.w);
    __half2 h2 = __floats2half2_rn(b.x, b.y);
    __half2 h3 = __floats2half2_rn(b.z, b.w);
    uint4 o;
    o.x = *reinterpret_cast<unsigned*>(&h0);
    o.y = *reinterpret_cast<unsigned*>(&h1);
    o.z = *reinterpret_cast<unsigned*>(&h2);
    o.w = *reinterpret_cast<unsigned*>(&h3);
    reinterpret_cast<uint4*>(&g_scratch[OFF_XH])[i] = o;
}

__global__ void deg_kernel(const int* __restrict__ ei) {
    int i = blockIdx.x * blockDim.x + threadIdx.x;
    if (i >= RR * EE) return;
    int r = i / EE, e = i - r * EE;
    int src = ei[(size_t)r * 2 * EE + e];
    int dst = ei[(size_t)r * 2 * EE + EE + e];
    atomicAdd(&g_scratch[OFF_SC_OUT + (size_t)r * NN + src], 1.f);
    atomicAdd(&g_scratch[OFF_SC_IN  + (size_t)r * NN + dst], 1.f);
}

#define SCAN_B 1024
#define SCAN_NBLK ((NBINS + SCAN_B - 1) / SCAN_B)   // 147

__global__ void scanA_kernel() {
    __shared__ int sm[SCAN_B];
    int tid = threadIdx.x;
    int i = blockIdx.x * SCAN_B + tid;
    int v = (i < NBINS) ? (int)g_scratch[OFF_SC_IN + i] : 0;
    sm[tid] = v;
    __syncthreads();
    for (int off = 1; off < SCAN_B; off <<= 1) {
        int t = (tid >= off) ? sm[tid - off] : 0;
        __syncthreads();
        sm[tid] += t;
        __syncthreads();
    }
    if (i < NBINS)
        reinterpret_cast<int*>(g_scratch)[OFF_OFFSET + i] = sm[tid] - v;
    if (tid == SCAN_B - 1)
        reinterpret_cast<int*>(g_scratch)[OFF_BLKSUM + blockIdx.x] = sm[tid];
}

__global__ void scanB_kernel() {
    __shared__ int sm[256];
    int tid = threadIdx.x;
    int* bs = reinterpret_cast<int*>(g_scratch) + OFF_BLKSUM;
    int v = (tid < SCAN_NBLK) ? bs[tid] : 0;
    sm[tid] = v;
    __syncthreads();
    for (int off = 1; off < 256; off <<= 1) {
        int t = (tid >= off) ? sm[tid - off] : 0;
        __syncthreads();
        sm[tid] += t;
        __syncthreads();
    }
    if (tid < SCAN_NBLK) bs[tid] = sm[tid] - v;
}

__global__ void scanC_kernel() {
    int i = blockIdx.x * blockDim.x + threadIdx.x;
    if (i >= NBINS) return;
    int* ip = reinterpret_cast<int*>(g_scratch);
    ip[OFF_OFFSET + i] += ip[OFF_BLKSUM + i / SCAN_B];
}

// edge placement: CSR by (r,dst), rsqrt-scales computed inline from raw counts
__global__ void place_kernel(const int* __restrict__ ei) {
    int i = blockIdx.x * blockDim.x + threadIdx.x;
    if (i >= RR * EE) return;
    int r = i / EE, e = i - r * EE;
    int src = ei[(size_t)r * 2 * EE + e];
    int dst = ei[(size_t)r * 2 * EE + EE + e];
    float dout = g_scratch[OFF_SC_OUT + (size_t)r * NN + src];
    float din  = g_scratch[OFF_SC_IN  + (size_t)r * NN + dst];
    float s = rsqrtf(fmaxf(dout, 1.f)) * rsqrtf(fmaxf(din, 1.f));
    int bin = r * NN + dst;
    int* ip = reinterpret_cast<int*>(g_scratch);
    int pos = ip[OFF_OFFSET + bin] + atomicAdd(&ip[OFF_CURSOR + bin], 1);
    uint2* edg = reinterpret_cast<uint2*>(&g_scratch[OFF_EDG]);
    uint2 rec;
    rec.x = (unsigned)src;
    rec.y = __float_as_uint(s);
    edg[pos] = rec;
}

// ================================================================ gather layer 1 (half in, fp32 accum, half out)
__global__ void gather1_kernel() {
    int dst = (blockIdx.x * blockDim.x + threadIdx.x) >> 5;
    int lane = threadIdx.x & 31;
    if (dst >= NN) return;
    const int* ip = reinterpret_cast<const int*>(g_scratch);
    const uint2* edg = reinterpret_cast<const uint2*>(&g_scratch[OFF_EDG]);
    const __half* xh = reinterpret_cast<const __half*>(&g_scratch[OFF_XH]);
    __half* aggh = reinterpret_cast<__half*>(&g_scratch[OFF_AGGH]);
    #pragma unroll
    for (int r = 0; r < RR; r++) {
        int bin = r * NN + dst;
        int st = ip[OFF_OFFSET + bin];
        int cnt = ip[OFF_CURSOR + bin];
        float4 a0 = make_float4(0.f, 0.f, 0.f, 0.f);
        float4 a1 = make_float4(0.f, 0.f, 0.f, 0.f);
        int p = 0;
        for (; p + 2 <= cnt; p += 2) {
            uint2 e0 = edg[st + p];
            uint2 e1 = edg[st + p + 1];
            float c0 = __uint_as_float(e0.y);
            float c1 = __uint_as_float(e1.y);
            uint2 w0 = *reinterpret_cast<const uint2*>(xh + (size_t)e0.x * FF + lane * 4);
            uint2 w1 = *reinterpret_cast<const uint2*>(xh + (size_t)e1.x * FF + lane * 4);
            float2 f0a = __half22float2(*reinterpret_cast<__half2*>(&w0.x));
            float2 f0b = __half22float2(*reinterpret_cast<__half2*>(&w0.y));
            float2 f1a = __half22float2(*reinterpret_cast<__half2*>(&w1.x));
            float2 f1b = __half22float2(*reinterpret_cast<__half2*>(&w1.y));
            a0.x = fmaf(c0, f0a.x, a0.x); a0.y = fmaf(c0, f0a.y, a0.y);
            a0.z = fmaf(c0, f0b.x, a0.z); a0.w = fmaf(c0, f0b.y, a0.w);
            a1.x = fmaf(c1, f1a.x, a1.x); a1.y = fmaf(c1, f1a.y, a1.y);
            a1.z = fmaf(c1, f1b.x, a1.z); a1.w = fmaf(c1, f1b.y, a1.w);
        }
        if (p < cnt) {
            uint2 e0 = edg[st + p];
            float c0 = __uint_as_float(e0.y);
            uint2 w0 = *reinterpret_cast<const uint2*>(xh + (size_t)e0.x * FF + lane * 4);
            float2 f0a = __half22float2(*reinterpret_cast<__half2*>(&w0.x));
            float2 f0b = __half22float2(*reinterpret_cast<__half2*>(&w0.y));
            a0.x = fmaf(c0, f0a.x, a0.x); a0.y = fmaf(c0, f0a.y, a0.y);
            a0.z = fmaf(c0, f0b.x, a0.z); a0.w = fmaf(c0, f0b.y, a0.w);
        }
        a0.x += a1.x; a0.y += a1.y; a0.z += a1.z; a0.w += a1.w;
        __half2 h01 = __floats2half2_rn(a0.x, a0.y);
        __half2 h23 = __floats2half2_rn(a0.z, a0.w);
        uint2 st2;
        st2.x = *reinterpret_cast<unsigned*>(&h01);
        st2.y = *reinterpret_cast<unsigned*>(&h23);
        *reinterpret_cast<uint2*>(aggh + (size_t)dst * 384 + r * FF + lane * 4) = st2;
    }
}

// ================================================================ gather layer 2 (half in) fused with uv
__global__ void gather2_uv_kernel(const float* __restrict__ Wlin) {
    int dst = (blockIdx.x * blockDim.x + threadIdx.x) >> 5;
    int lane = threadIdx.x & 31;
    if (dst >= NN) return;
    const int* ip = reinterpret_cast<const int*>(g_scratch);
    const uint2* edg = reinterpret_cast<const uint2*>(&g_scratch[OFF_EDG]);
    const __half* zh = reinterpret_cast<const __half*>(&g_scratch[OFF_AGGH]);
    float4 a0 = make_float4(0.f, 0.f, 0.f, 0.f);
    float4 a1 = make_float4(0.f, 0.f, 0.f, 0.f);
    #pragma unroll
    for (int r = 0; r < RR; r++) {
        int bin = r * NN + dst;
        int st = ip[OFF_OFFSET + bin];
        int cnt = ip[OFF_CURSOR + bin];
        int p = 0;
        for (; p + 2 <= cnt; p += 2) {
            uint2 e0 = edg[st + p];
            uint2 e1 = edg[st + p + 1];
            float c0 = __uint_as_float(e0.y);
            float c1 = __uint_as_float(e1.y);
            uint2 w0 = *reinterpret_cast<const uint2*>(zh + (size_t)e0.x * 384 + r * FF + lane * 4);
            uint2 w1 = *reinterpret_cast<const uint2*>(zh + (size_t)e1.x * 384 + r * FF + lane * 4);
            float2 f0a = __half22float2(*reinterpret_cast<__half2*>(&w0.x));
            float2 f0b = __half22float2(*reinterpret_cast<__half2*>(&w0.y));
            float2 f1a = __half22float2(*reinterpret_cast<__half2*>(&w1.x));
            float2 f1b = __half22float2(*reinterpret_cast<__half2*>(&w1.y));
            a0.x = fmaf(c0, f0a.x, a0.x); a0.y = fmaf(c0, f0a.y, a0.y);
            a0.z = fmaf(c0, f0b.x, a0.z); a0.w = fmaf(c0, f0b.y, a0.w);
            a1.x = fmaf(c1, f1a.x, a1.x); a1.y = fmaf(c1, f1a.y, a1.y);
            a1.z = fmaf(c1, f1b.x, a1.z); a1.w = fmaf(c1, f1b.y, a1.w);
        }
        if (p < cnt) {
            uint2 e0 = edg[st + p];
            float c0 = __uint_as_float(e0.y);
            uint2 w0 = *reinterpret_cast<const uint2*>(zh + (size_t)e0.x * 384 + r * FF + lane * 4);
            float2 f0a = __half22float2(*reinterpret_cast<__half2*>(&w0.x));
            float2 f0b = __half22float2(*reinterpret_cast<__half2*>(&w0.y));
            a0.x = fmaf(c0, f0a.x, a0.x); a0.y = fmaf(c0, f0a.y, a0.y);
            a0.z = fmaf(c0, f0b.x, a0.z); a0.w = fmaf(c0, f0b.y, a0.w);
        }
    }
    a0.x += a1.x; a0.y += a1.y; a0.z += a1.z; a0.w += a1.w;
    const float inv3 = (1.f / 3.f);
    float4 bb = *reinterpret_cast<const float4*>(&g_scratch[OFF_BS2 + lane * 4]);
    a0.x = fmaxf((a0.x + bb.x) * inv3, 0.f);
    a0.y = fmaxf((a0.y + bb.y) * inv3, 0.f);
    a0.z = fmaxf((a0.z + bb.z) * inv3, 0.f);
    a0.w = fmaxf((a0.w + bb.w) * inv3, 0.f);
    const float4* wv = reinterpret_cast<const float4*>(Wlin);
    float4 wl = wv[lane];
    float4 wh = wv[32 + lane];
    float su = a0.x * wl.x + a0.y * wl.y + a0.z * wl.z + a0.w * wl.w;
    float sv = a0.x * wh.x + a0.y * wh.y + a0.z * wh.z + a0.w * wh.w;
    #pragma unroll
    for (int o = 16; o > 0; o >>= 1) {
        su += __shfl_down_sync(0xffffffffu, su, o);
        sv += __shfl_down_sync(0xffffffffu, sv, o);
    }
    if (lane == 0) {
        g_scratch[OFF_U + dst] = su;
        g_scratch[OFF_V + dst] = sv;
    }
}

// ================================================================ fp16 tensor-core GEMM (m16n8k16)
#define BM 128
#define BN 64
#define BK 32
#define BKP 40   // +8 halves pad -> conflict-free fragment loads

__device__ __forceinline__ void mma_fp16(float* d, const unsigned* a, const unsigned* b) {
    asm volatile("mma.sync.aligned.m16n8k16.row.col.f32.f16.f16.f32 "
                 "{%0,%1,%2,%3}, {%4,%5,%6,%7}, {%8,%9}, {%0,%1,%2,%3};"
                 : "+f"(d[0]), "+f"(d[1]), "+f"(d[2]), "+f"(d[3])
                 : "r"(a[0]), "r"(a[1]), "r"(a[2]), "r"(a[3]),
                   "r"(b[0]), "r"(b[1]));
}

__global__ __launch_bounds__(256) void gemm_fp16_kernel(
    const __half* __restrict__ A, const __half* __restrict__ Bt,
    const float* __restrict__ bias, __half* __restrict__ C,
    int M, int K, int Ncol, int doRelu, float scale)
{
    __shared__ __half As[BM][BKP];
    __shared__ __half Bs[BN][BKP];

    int tid = threadIdx.x;
    int warp = tid >> 5;
    int lane = tid & 31;
    int wr = warp >> 1;
    int wc = warp & 1;
    int bm = blockIdx.y * BM, bn = blockIdx.x * BN;
    int tg = lane >> 2;
    int tq = lane & 3;

    float acc[2][4][4];
    #pragma unroll
    for (int i = 0; i < 2; i++)
        #pragma unroll
        for (int j = 0; j < 4; j++)
            #pragma unroll
            for (int q = 0; q < 4; q++) acc[i][j][q] = 0.f;

    int ld_row = tid >> 2;
    int ld_c8 = tid & 3;

    for (int k0 = 0; k0 < K; k0 += BK) {
        #pragma unroll
        for (int p = 0; p < 2; p++) {
            int m = bm + p * 64 + ld_row;
            uint4 v = make_uint4(0, 0, 0, 0);
            if (m < M) v = *reinterpret_cast<const uint4*>(A + (size_t)m * K + k0 + ld_c8 * 8);
            *reinterpret_cast<uint4*>(&As[p * 64 + ld_row][ld_c8 * 8]) = v;
        }
        {
            uint4 v = *reinterpret_cast<const uint4*>(Bt + (size_t)(bn + ld_row) * K + k0 + ld_c8 * 8);
            *reinterpret_cast<uint4*>(&Bs[ld_row][ld_c8 * 8]) = v;
        }
        __syncthreads();

        #pragma unroll
        for (int kk = 0; kk < BK; kk += 16) {
            unsigned af[2][4], bf[4][2];
            #pragma unroll
            for (int i = 0; i < 2; i++) {
                int mb = wr * 32 + i * 16;
                af[i][0] = *reinterpret_cast<unsigned*>(&As[mb + tg    ][kk + 2 * tq    ]);
                af[i][1] = *reinterpret_cast<unsigned*>(&As[mb + tg + 8][kk + 2 * tq    ]);
                af[i][2] = *reinterpret_cast<unsigned*>(&As[mb + tg    ][kk + 2 * tq + 8]);
                af[i][3] = *reinterpret_cast<unsigned*>(&As[mb + tg + 8][kk + 2 * tq + 8]);
            }
            #pragma unroll
            for (int j = 0; j < 4; j++) {
                int nb = wc * 32 + j * 8;
                bf[j][0] = *reinterpret_cast<unsigned*>(&Bs[nb + tg][kk + 2 * tq    ]);
                bf[j][1] = *reinterpret_cast<unsigned*>(&Bs[nb + tg][kk + 2 * tq + 8]);
            }
            #pragma unroll
            for (int i = 0; i < 2; i++)
                #pragma unroll
                for (int j = 0; j < 4; j++)
                    mma_fp16(acc[i][j], af[i], bf[j]);
        }
        __syncthreads();
    }

    #pragma unroll
    for (int i = 0; i < 2; i++) {
        #pragma unroll
        for (int j = 0; j < 4; j++) {
            int col = bn + wc * 32 + j * 8 + tq * 2;
            float b0 = 0.f, b1 = 0.f;
            if (bias) { b0 = bias[col]; b1 = bias[col + 1]; }
            #pragma unroll
            for (int h = 0; h < 2; h++) {
                int row = bm + wr * 32 + i * 16 + tg + h * 8;
                if (row < M) {
                    float o0 = (acc[i][j][2 * h + 0] + b0) * scale;
                    float o1 = (acc[i][j][2 * h + 1] + b1) * scale;
                    if (doRelu) { o0 = fmaxf(o0, 0.f); o1 = fmaxf(o1, 0.f); }
                    *reinterpret_cast<__half2*>(C + (size_t)row * Ncol + col) =
                        __floats2half2_rn(o0, o1);
                }
            }
        }
    }
}

// ================================================================ pair head
__global__ void pairs_kernel(const int* __restrict__ ei, const int* __restrict__ np,
                             const float* __restrict__ blin, float* __restrict__ out) {
    int i = blockIdx.x * blockDim.x + threadIdx.x;
    if (i >= NPAIRS) return;
    int src, dst;
    if (i < RR * EE) {
        int r = i / EE, e = i - r * EE;
        src = ei[(size_t)r * 2 * EE + e];
        dst = ei[(size_t)r * 2 * EE + EE + e];
    } else {
        int j = i - RR * EE;
        src = np[2 * j];
        dst = np[2 * j + 1];
    }
    float z = g_scratch[OFF_U + src] + g_scratch[OFF_V + dst] + blin[0];
    out[i] = 1.f / (1.f + expf(-z));
}

// ================================================================ launch
extern "C" void kernel_launch(void* const* d_in, const int* in_sizes, int n_in,
                              void* d_out, int out_size) {
    const float* x    = (const float*)d_in[0];
    const int*   ei   = (const int*)  d_in[1];
    const int*   np   = (const int*)  d_in[2];
    const float* W1   = (const float*)d_in[3];
    const float* b1   = (const float*)d_in[4];
    const float* W2   = (const float*)d_in[5];
    const float* b2   = (const float*)d_in[6];
    const float* Wlin = (const float*)d_in[7];
    const float* blin = (const float*)d_in[8];
    float* out = (float*)d_out;

    void* base = nullptr;
    cudaGetSymbolAddress(&base, g_scratch);
    float* fb = (float*)base;
    __half* aggh = (__half*)(fb + OFF_AGGH);
    __half* h1h  = (__half*)(fb + OFF_H1H);
    __half* bt1h = (__half*)(fb + OFF_BT1H);
    __half* bt2h = (__half*)(fb + OFF_BT2H);
    float* bs1   = fb + OFF_BS1;

    // 1. zero scales + cursors
    zero_kernel<<<(unsigned)((ZERO_FLOATS / 4 + 255) / 256), 256>>>();
    // 2. fused weight/bias pack + x->half
    pack_kernel<<<(2 * HH * RR * FF + HH + FF + 255) / 256, 256>>>(W1, W2, b1, b2);
    xh_kernel<<<(NN * FF / 8 + 255) / 256, 256>>>(x);
    // 3. degrees
    deg_kernel<<<(RR * EE + 255) / 256, 256>>>(ei);
    // 4. CSR offsets
    scanA_kernel<<<SCAN_NBLK, SCAN_B>>>();
    scanB_kernel<<<1, 256>>>();
    scanC_kernel<<<(NBINS + 255) / 256, 256>>>();
    // 5. edge placement (rsqrt folded)
    place_kernel<<<(RR * EE + 255) / 256, 256>>>(ei);
    // 6. layer-1 gather (half in/out)
    gather1_kernel<<<(NN * 32 + 255) / 256, 256>>>();
    // 7. GEMM1: h1 = relu((agg @ W1 + bs1)/3)
    gemm_fp16_kernel<<<dim3(HH / BN, (NN + BM - 1) / BM), 256>>>(
        aggh, bt1h, bs1, h1h, NN, RR * FF, HH, 1, 1.f / 3.f);
    // 8. GEMM2: z = h1 @ W2P -> reuse aggh
    gemm_fp16_kernel<<<dim3((RR * FF) / BN, (NN + BM - 1) / BM), 256>>>(
        h1h, bt2h, nullptr, aggh, NN, HH, RR * FF, 0, 1.f);
    // 9. layer-2 gather + u/v
    gather2_uv_kernel<<<(NN * 32 + 255) / 256, 256>>>(Wlin);
    // 10. pair outputs
    pairs_kernel<<<(NPAIRS + 255) / 256, 256>>>(ei, np, blin, out);
}